// round 1
// baseline (speedup 1.0000x reference)
#include <cuda_runtime.h>
#include <cstdint>

// Problem dims
// B=256, T=256, D=96, H=6, E=16, DFF=384
#define NTOK 65536              // B*T
#define NEL  6291456            // NTOK*96

// ---------------- scratch (device globals; no allocations) ----------------
__device__ float g_h [NTOK * 96];    // LN output, later attn output (concat heads), later LN2 out
__device__ float g_q [NTOK * 96];    // [B*H, T, E]
__device__ float g_k [NTOK * 96];
__device__ float g_v [NTOK * 96];
__device__ float g_x1[NTOK * 96];    // residual after attention branch
__device__ float g_f [NTOK * 384];   // FF hidden

// ---------------- JAX threefry-2x32 (20 rounds) ----------------
__host__ __device__ __forceinline__ void tf2x32(unsigned k0, unsigned k1,
                                                unsigned x0, unsigned x1,
                                                unsigned &o0, unsigned &o1) {
  unsigned k2 = k0 ^ k1 ^ 0x1BD11BDAu;
  unsigned v0 = x0 + k0, v1 = x1 + k1;
#define TFR(r) { v0 += v1; v1 = (v1 << (r)) | (v1 >> (32 - (r))); v1 ^= v0; }
  TFR(13) TFR(15) TFR(26) TFR(6)   v0 += k1; v1 += k2 + 1u;
  TFR(17) TFR(29) TFR(16) TFR(24)  v0 += k2; v1 += k0 + 2u;
  TFR(13) TFR(15) TFR(26) TFR(6)   v0 += k0; v1 += k1 + 3u;
  TFR(17) TFR(29) TFR(16) TFR(24)  v0 += k1; v1 += k2 + 4u;
  TFR(13) TFR(15) TFR(26) TFR(6)   v0 += k2; v1 += k0 + 5u;
#undef TFR
  o0 = v0; o1 = v1;
}

// jax.random.normal element (threefry_partitionable path, 32-bit draws):
// bits = out0 ^ out1 of cipher(key, (hi32(i)=0, lo32(i)=i)); then JAX uniform->erfinv.
__device__ __forceinline__ float jax_noise(unsigned k0, unsigned k1, unsigned idx) {
  unsigned o0, o1;
  tf2x32(k0, k1, 0u, idx, o0, o1);
  unsigned bits = o0 ^ o1;
  float u = __uint_as_float((bits >> 9) | 0x3f800000u) - 1.0f;   // [0,1)
  const float lo = -0.99999994f;                                  // nextafter(-1,0) fp32
  float val = u * 1.99999994f + lo;                               // u*(1-lo)+lo
  val = fmaxf(lo, val);
  return 0.1f * (1.4142135381698608f * erfinvf(val));             // NOISE_STD * sqrt(2)*erfinv
}

// ---------------- LayerNorm: one warp per row of 96 ----------------
__global__ void __launch_bounds__(256) ln_kernel(const float* __restrict__ in,
                                                 const float* __restrict__ g,
                                                 const float* __restrict__ b) {
  const float* src = in ? in : g_x1;      // null -> LN2 over residual buffer
  int row  = blockIdx.x * 8 + (threadIdx.x >> 5);
  int lane = threadIdx.x & 31;
  const float* xr = src + row * 96;
  float v0 = xr[lane], v1 = xr[lane + 32], v2 = xr[lane + 64];
  float s  = v0 + v1 + v2;
  float sq = v0 * v0 + v1 * v1 + v2 * v2;
#pragma unroll
  for (int o = 16; o; o >>= 1) {
    s  += __shfl_xor_sync(0xffffffffu, s, o);
    sq += __shfl_xor_sync(0xffffffffu, sq, o);
  }
  float m   = s * (1.0f / 96.0f);
  float var = sq * (1.0f / 96.0f) - m * m;
  float r   = rsqrtf(var + 1e-5f);
  float* out = g_h + row * 96;
  out[lane]      = (v0 - m) * r * g[lane]      + b[lane];
  out[lane + 32] = (v1 - m) * r * g[lane + 32] + b[lane + 32];
  out[lane + 64] = (v2 - m) * r * g[lane + 64] + b[lane + 64];
}

// ---------------- GEMM tile config: 64 rows x 96 cols, BK=32, 256 thr ----------------
// thread (cx,ry): cx = tid&15 covers 6 cols, ry = tid>>4 covers 4 rows.

// QKV: h[65536,96] @ Wx[h,d,e] -> q/k/v stored [B*H, T, E]
__global__ void __launch_bounds__(256) qkv_kernel(const float* __restrict__ Wq,
                                                  const float* __restrict__ Wk,
                                                  const float* __restrict__ Wv) {
  const float* W  = (blockIdx.y == 0) ? Wq : (blockIdx.y == 1) ? Wk : Wv;
  float*       Out = (blockIdx.y == 0) ? g_q : (blockIdx.y == 1) ? g_k : g_v;
  __shared__ float As[32][65];
  __shared__ float Bs[32][96];
  int row0 = blockIdx.x * 64;
  int tid = threadIdx.x;
  int cx = tid & 15, ry = tid >> 4;
  float acc[4][6] = {};
  for (int k0 = 0; k0 < 96; k0 += 32) {
#pragma unroll
    for (int i = 0; i < 8; i++) {
      int idx = tid + i * 256; int r = idx >> 5, c = idx & 31;
      As[c][r] = g_h[(row0 + r) * 96 + k0 + c];
    }
#pragma unroll
    for (int i = 0; i < 12; i++) {
      int idx = tid + i * 256; int r = idx / 96, c = idx % 96;
      Bs[r][c] = W[(c >> 4) * 1536 + (k0 + r) * 16 + (c & 15)];   // Wx[h,d,e]
    }
    __syncthreads();
#pragma unroll
    for (int kk = 0; kk < 32; kk++) {
      float a[4], bb[6];
#pragma unroll
      for (int i = 0; i < 4; i++) a[i] = As[kk][ry * 4 + i];
#pragma unroll
      for (int j = 0; j < 6; j++) bb[j] = Bs[kk][cx * 6 + j];
#pragma unroll
      for (int i = 0; i < 4; i++)
#pragma unroll
        for (int j = 0; j < 6; j++) acc[i][j] += a[i] * bb[j];
    }
    __syncthreads();
  }
#pragma unroll
  for (int i = 0; i < 4; i++) {
    int tok = row0 + ry * 4 + i;
    int b_ = tok >> 8, t_ = tok & 255;
#pragma unroll
    for (int j = 0; j < 6; j++) {
      int c = cx * 6 + j;
      Out[(((b_ * 6 + (c >> 4)) * 256 + t_) * 16) + (c & 15)] = acc[i][j];
    }
  }
}

// Attention: one block per (b,h); one thread per query row; online softmax.
__global__ void __launch_bounds__(256) attn_kernel() {
  int bh = blockIdx.x;
  __shared__ __align__(16) float ks[256][16];
  __shared__ __align__(16) float vs[256][16];
  const float* kb = g_k + bh * (256 * 16);
  const float* vb = g_v + bh * (256 * 16);
  for (int i = threadIdx.x; i < 1024; i += 256) {
    reinterpret_cast<float4*>(&ks[0][0])[i] = reinterpret_cast<const float4*>(kb)[i];
    reinterpret_cast<float4*>(&vs[0][0])[i] = reinterpret_cast<const float4*>(vb)[i];
  }
  __syncthreads();
  int t = threadIdx.x;
  const float4* qr = reinterpret_cast<const float4*>(g_q + (bh * 256 + t) * 16);
  float4 q0 = qr[0], q1 = qr[1], q2 = qr[2], q3 = qr[3];
  float m = -1e30f, l = 0.0f;
  float acc[16] = {};
  for (int s = 0; s <= t; s++) {
    const float4* kr = reinterpret_cast<const float4*>(ks[s]);
    float4 ka = kr[0], kb4 = kr[1], kc = kr[2], kd = kr[3];
    float dot = q0.x * ka.x  + q0.y * ka.y  + q0.z * ka.z  + q0.w * ka.w
              + q1.x * kb4.x + q1.y * kb4.y + q1.z * kb4.z + q1.w * kb4.w
              + q2.x * kc.x  + q2.y * kc.y  + q2.z * kc.z  + q2.w * kc.w
              + q3.x * kd.x  + q3.y * kd.y  + q3.z * kd.z  + q3.w * kd.w;
    dot *= 0.25f;                                   // E^-0.5
    float mn   = fmaxf(m, dot);
    float corr = __expf(m - mn);
    float p    = __expf(dot - mn);
    l = l * corr + p;
    const float4* vr = reinterpret_cast<const float4*>(vs[s]);
#pragma unroll
    for (int j = 0; j < 4; j++) {
      float4 vv = vr[j];
      acc[4*j+0] = acc[4*j+0] * corr + p * vv.x;
      acc[4*j+1] = acc[4*j+1] * corr + p * vv.y;
      acc[4*j+2] = acc[4*j+2] * corr + p * vv.z;
      acc[4*j+3] = acc[4*j+3] * corr + p * vv.w;
    }
    m = mn;
  }
  float inv = 1.0f / l;
  int b_ = bh / 6, h_ = bh % 6;
  float* orow = g_h + (b_ * 256 + t) * 96 + h_ * 16;   // concat-heads layout
#pragma unroll
  for (int e = 0; e < 16; e++) orow[e] = acc[e] * inv;
}

// Projection + residual + noise1: x1 = x + o@Wp + bp + noise
__global__ void __launch_bounds__(256) proj_kernel(const float* __restrict__ Wp,
                                                   const float* __restrict__ bp,
                                                   const float* __restrict__ x,
                                                   unsigned nk0, unsigned nk1v) {
  __shared__ float As[32][65];
  __shared__ float Bs[32][96];
  int row0 = blockIdx.x * 64;
  int tid = threadIdx.x;
  int cx = tid & 15, ry = tid >> 4;
  float acc[4][6] = {};
  for (int k0 = 0; k0 < 96; k0 += 32) {
#pragma unroll
    for (int i = 0; i < 8; i++) {
      int idx = tid + i * 256; int r = idx >> 5, c = idx & 31;
      As[c][r] = g_h[(row0 + r) * 96 + k0 + c];
    }
#pragma unroll
    for (int i = 0; i < 12; i++) {
      int idx = tid + i * 256; int r = idx / 96, c = idx % 96;
      Bs[r][c] = Wp[(k0 + r) * 96 + c];
    }
    __syncthreads();
#pragma unroll
    for (int kk = 0; kk < 32; kk++) {
      float a[4], bb[6];
#pragma unroll
      for (int i = 0; i < 4; i++) a[i] = As[kk][ry * 4 + i];
#pragma unroll
      for (int j = 0; j < 6; j++) bb[j] = Bs[kk][cx * 6 + j];
#pragma unroll
      for (int i = 0; i < 4; i++)
#pragma unroll
        for (int j = 0; j < 6; j++) acc[i][j] += a[i] * bb[j];
    }
    __syncthreads();
  }
#pragma unroll
  for (int i = 0; i < 4; i++) {
    int tok = row0 + ry * 4 + i;
#pragma unroll
    for (int j = 0; j < 6; j++) {
      int c = cx * 6 + j;
      int idx = tok * 96 + c;
      g_x1[idx] = x[idx] + acc[i][j] + bp[c] + jax_noise(nk0, nk1v, (unsigned)idx);
    }
  }
}

// FF1: relu(h2 @ W1 + b1) -> g_f  (col group via blockIdx.y, 4 groups of 96)
__global__ void __launch_bounds__(256) ff1_kernel(const float* __restrict__ W1,
                                                  const float* __restrict__ b1) {
  __shared__ float As[32][65];
  __shared__ float Bs[32][96];
  int row0 = blockIdx.x * 64;
  int co = blockIdx.y * 96;
  int tid = threadIdx.x;
  int cx = tid & 15, ry = tid >> 4;
  float acc[4][6] = {};
  for (int k0 = 0; k0 < 96; k0 += 32) {
#pragma unroll
    for (int i = 0; i < 8; i++) {
      int idx = tid + i * 256; int r = idx >> 5, c = idx & 31;
      As[c][r] = g_h[(row0 + r) * 96 + k0 + c];
    }
#pragma unroll
    for (int i = 0; i < 12; i++) {
      int idx = tid + i * 256; int r = idx / 96, c = idx % 96;
      Bs[r][c] = W1[(k0 + r) * 384 + co + c];
    }
    __syncthreads();
#pragma unroll
    for (int kk = 0; kk < 32; kk++) {
      float a[4], bb[6];
#pragma unroll
      for (int i = 0; i < 4; i++) a[i] = As[kk][ry * 4 + i];
#pragma unroll
      for (int j = 0; j < 6; j++) bb[j] = Bs[kk][cx * 6 + j];
#pragma unroll
      for (int i = 0; i < 4; i++)
#pragma unroll
        for (int j = 0; j < 6; j++) acc[i][j] += a[i] * bb[j];
    }
    __syncthreads();
  }
#pragma unroll
  for (int i = 0; i < 4; i++) {
    int tok = row0 + ry * 4 + i;
#pragma unroll
    for (int j = 0; j < 6; j++) {
      int c = co + cx * 6 + j;
      g_f[tok * 384 + c] = fmaxf(acc[i][j] + b1[c], 0.0f);
    }
  }
}

// FF2 + residual + noise2 -> d_out
__global__ void __launch_bounds__(256) ff2_kernel(const float* __restrict__ W2,
                                                  const float* __restrict__ b2,
                                                  float* __restrict__ out,
                                                  unsigned nk0, unsigned nk1v) {
  __shared__ float As[32][65];
  __shared__ float Bs[32][96];
  int row0 = blockIdx.x * 64;
  int tid = threadIdx.x;
  int cx = tid & 15, ry = tid >> 4;
  float acc[4][6] = {};
  for (int k0 = 0; k0 < 384; k0 += 32) {
#pragma unroll
    for (int i = 0; i < 8; i++) {
      int idx = tid + i * 256; int r = idx >> 5, c = idx & 31;
      As[c][r] = g_f[(row0 + r) * 384 + k0 + c];
    }
#pragma unroll
    for (int i = 0; i < 12; i++) {
      int idx = tid + i * 256; int r = idx / 96, c = idx % 96;
      Bs[r][c] = W2[(k0 + r) * 96 + c];
    }
    __syncthreads();
#pragma unroll
    for (int kk = 0; kk < 32; kk++) {
      float a[4], bb[6];
#pragma unroll
      for (int i = 0; i < 4; i++) a[i] = As[kk][ry * 4 + i];
#pragma unroll
      for (int j = 0; j < 6; j++) bb[j] = Bs[kk][cx * 6 + j];
#pragma unroll
      for (int i = 0; i < 4; i++)
#pragma unroll
        for (int j = 0; j < 6; j++) acc[i][j] += a[i] * bb[j];
    }
    __syncthreads();
  }
#pragma unroll
  for (int i = 0; i < 4; i++) {
    int tok = row0 + ry * 4 + i;
#pragma unroll
    for (int j = 0; j < 6; j++) {
      int c = cx * 6 + j;
      int idx = tok * 96 + c;
      out[idx] = g_x1[idx] + acc[i][j] + b2[c] + jax_noise(nk0, nk1v, (unsigned)idx);
    }
  }
}

extern "C" void kernel_launch(void* const* d_in, const int* in_sizes, int n_in,
                              void* d_out, int out_size) {
  (void)in_sizes; (void)n_in; (void)out_size;
  const float* x    = (const float*)d_in[0];
  const float* Wq   = (const float*)d_in[1];
  const float* Wk   = (const float*)d_in[2];
  const float* Wv   = (const float*)d_in[3];
  const float* Wp   = (const float*)d_in[4];
  const float* bp   = (const float*)d_in[5];
  const float* ln1g = (const float*)d_in[6];
  const float* ln1b = (const float*)d_in[7];
  const float* ln2g = (const float*)d_in[8];
  const float* ln2b = (const float*)d_in[9];
  const float* W1   = (const float*)d_in[10];
  const float* b1   = (const float*)d_in[11];
  const float* W2   = (const float*)d_in[12];
  const float* b2   = (const float*)d_in[13];
  float* out = (float*)d_out;

  // jax.random.split(key(42), 2) under threefry_partitionable:
  // nk_i = threefry2x32(key=(0,42), counts=(0, i))
  unsigned nk1_0, nk1_1, nk2_0, nk2_1;
  tf2x32(0u, 42u, 0u, 0u, nk1_0, nk1_1);
  tf2x32(0u, 42u, 0u, 1u, nk2_0, nk2_1);

  ln_kernel  <<<8192, 256>>>(x, ln1g, ln1b);
  qkv_kernel <<<dim3(1024, 3), 256>>>(Wq, Wk, Wv);
  attn_kernel<<<1536, 256>>>();
  proj_kernel<<<1024, 256>>>(Wp, bp, x, nk1_0, nk1_1);
  ln_kernel  <<<8192, 256>>>(nullptr, ln2g, ln2b);
  ff1_kernel <<<dim3(1024, 4), 256>>>(W1, b1);
  ff2_kernel <<<1024, 256>>>(W2, b2, out, nk2_0, nk2_1);
}

// round 2
// speedup vs baseline: 1.0867x; 1.0867x over previous
#include <cuda_runtime.h>
#include <cstdint>

// Problem dims: B=256, T=256, D=96, H=6, E=16, DFF=384
#define NTOK 65536              // B*T

// ---------------- scratch (device globals; no allocations) ----------------
__device__ float g_h [NTOK * 96];    // LN output / attn concat output / LN2 out
__device__ float g_q [NTOK * 96];    // [B*H, T, E]
__device__ float g_k [NTOK * 96];
__device__ float g_v [NTOK * 96];
__device__ float g_x1[NTOK * 96];    // residual after attention branch
__device__ float g_f [NTOK * 384];   // FF hidden

// ---------------- packed f32x2 helpers ----------------
__device__ __forceinline__ unsigned long long f2x2(float lo, float hi) {
  unsigned long long r; asm("mov.b64 %0, {%1, %2};" : "=l"(r) : "f"(lo), "f"(hi)); return r;
}
__device__ __forceinline__ unsigned long long fma2(unsigned long long a, unsigned long long b, unsigned long long c) {
  unsigned long long d; asm("fma.rn.f32x2 %0, %1, %2, %3;" : "=l"(d) : "l"(a), "l"(b), "l"(c)); return d;
}
__device__ __forceinline__ unsigned long long mul2(unsigned long long a, unsigned long long b) {
  unsigned long long d; asm("mul.rn.f32x2 %0, %1, %2;" : "=l"(d) : "l"(a), "l"(b)); return d;
}
__device__ __forceinline__ void unpack2(unsigned long long v, float &lo, float &hi) {
  asm("mov.b64 {%0, %1}, %2;" : "=f"(lo), "=f"(hi) : "l"(v));
}

// ---------------- JAX threefry-2x32 (20 rounds) ----------------
__host__ __device__ __forceinline__ void tf2x32(unsigned k0, unsigned k1,
                                                unsigned x0, unsigned x1,
                                                unsigned &o0, unsigned &o1) {
  unsigned k2 = k0 ^ k1 ^ 0x1BD11BDAu;
  unsigned v0 = x0 + k0, v1 = x1 + k1;
#define TFR(r) { v0 += v1; v1 = (v1 << (r)) | (v1 >> (32 - (r))); v1 ^= v0; }
  TFR(13) TFR(15) TFR(26) TFR(6)   v0 += k1; v1 += k2 + 1u;
  TFR(17) TFR(29) TFR(16) TFR(24)  v0 += k2; v1 += k0 + 2u;
  TFR(13) TFR(15) TFR(26) TFR(6)   v0 += k0; v1 += k1 + 3u;
  TFR(17) TFR(29) TFR(16) TFR(24)  v0 += k1; v1 += k2 + 4u;
  TFR(13) TFR(15) TFR(26) TFR(6)   v0 += k2; v1 += k0 + 5u;
#undef TFR
  o0 = v0; o1 = v1;
}

__device__ __forceinline__ float jax_noise(unsigned k0, unsigned k1, unsigned idx) {
  unsigned o0, o1;
  tf2x32(k0, k1, 0u, idx, o0, o1);
  unsigned bits = o0 ^ o1;
  float u = __uint_as_float((bits >> 9) | 0x3f800000u) - 1.0f;
  const float lo = -0.99999994f;
  float val = u * 1.99999994f + lo;
  val = fmaxf(lo, val);
  return 0.1f * (1.4142135381698608f * erfinvf(val));
}

// ---------------- LayerNorm: one warp per row of 96 ----------------
__global__ void __launch_bounds__(256) ln_kernel(const float* __restrict__ in,
                                                 const float* __restrict__ g,
                                                 const float* __restrict__ b) {
  const float* src = in ? in : g_x1;
  int row  = blockIdx.x * 8 + (threadIdx.x >> 5);
  int lane = threadIdx.x & 31;
  const float* xr = src + row * 96;
  float v0 = xr[lane], v1 = xr[lane + 32], v2 = xr[lane + 64];
  float s  = v0 + v1 + v2;
  float sq = v0 * v0 + v1 * v1 + v2 * v2;
#pragma unroll
  for (int o = 16; o; o >>= 1) {
    s  += __shfl_xor_sync(0xffffffffu, s, o);
    sq += __shfl_xor_sync(0xffffffffu, sq, o);
  }
  float m   = s * (1.0f / 96.0f);
  float var = sq * (1.0f / 96.0f) - m * m;
  float r   = rsqrtf(var + 1e-5f);
  float* out = g_h + row * 96;
  out[lane]      = (v0 - m) * r * g[lane]      + b[lane];
  out[lane + 32] = (v1 - m) * r * g[lane + 32] + b[lane + 32];
  out[lane + 64] = (v2 - m) * r * g[lane + 64] + b[lane + 64];
}

// ============ GEMM: 128 rows x 96 cols block tile, BK=32, 256 threads ============
// thread (cx,ry): cx = tid&15 -> 6 cols, ry = tid>>4 -> 8 rows (as 4 row-pairs).
// As[k][row] transposed in smem (pad 130 keeps 8B alignment, 2-way store conflicts only).

#define GEMM_SMEM \
  __shared__ float As[32][130]; \
  __shared__ float Bs[32][96];

#define GEMM_LOAD_A(SRC, LDK) \
  _Pragma("unroll") \
  for (int i = 0; i < 4; i++) { \
    int f = tid + i * 256; int r = f >> 3, cq = f & 7; \
    float4 v = *reinterpret_cast<const float4*>(&(SRC)[(row0 + r) * (LDK) + k0 + cq * 4]); \
    As[cq*4+0][r] = v.x; As[cq*4+1][r] = v.y; As[cq*4+2][r] = v.z; As[cq*4+3][r] = v.w; \
  }

#define GEMM_MAINLOOP \
  _Pragma("unroll") \
  for (int kk = 0; kk < 32; kk++) { \
    unsigned long long a[4]; \
    _Pragma("unroll") \
    for (int rp = 0; rp < 4; rp++) \
      a[rp] = *reinterpret_cast<const unsigned long long*>(&As[kk][ry * 8 + 2 * rp]); \
    unsigned long long bd[6]; \
    _Pragma("unroll") \
    for (int j = 0; j < 6; j++) { float bv = Bs[kk][cx * 6 + j]; bd[j] = f2x2(bv, bv); } \
    _Pragma("unroll") \
    for (int rp = 0; rp < 4; rp++) \
      _Pragma("unroll") \
      for (int j = 0; j < 6; j++) acc[rp][j] = fma2(a[rp], bd[j], acc[rp][j]); \
  }

// QKV: g_h[65536,96] @ Wx[h,d,e] -> q/k/v stored [B*H, T, E]
__global__ void __launch_bounds__(256) qkv_kernel(const float* __restrict__ Wq,
                                                  const float* __restrict__ Wk,
                                                  const float* __restrict__ Wv) {
  const float* W   = (blockIdx.y == 0) ? Wq : (blockIdx.y == 1) ? Wk : Wv;
  float*       Out = (blockIdx.y == 0) ? g_q : (blockIdx.y == 1) ? g_k : g_v;
  GEMM_SMEM
  int row0 = blockIdx.x * 128;
  int tid = threadIdx.x;
  int cx = tid & 15, ry = tid >> 4;
  unsigned long long acc[4][6] = {};
  for (int k0 = 0; k0 < 96; k0 += 32) {
    GEMM_LOAD_A(g_h, 96)
#pragma unroll
    for (int i = 0; i < 12; i++) {
      int idx = tid + i * 256; int r = idx / 96, c = idx % 96;
      Bs[r][c] = W[(c >> 4) * 1536 + (k0 + r) * 16 + (c & 15)];
    }
    __syncthreads();
    GEMM_MAINLOOP
    __syncthreads();
  }
#pragma unroll
  for (int rp = 0; rp < 4; rp++) {
#pragma unroll
    for (int j = 0; j < 6; j++) {
      float lo, hi; unpack2(acc[rp][j], lo, hi);
      int c = cx * 6 + j;
      int tok0 = row0 + ry * 8 + 2 * rp;
      int b0 = tok0 >> 8, t0 = tok0 & 255;
      Out[((b0 * 6 + (c >> 4)) * 256 + t0) * 16 + (c & 15)] = lo;
      int tok1 = tok0 + 1;
      int b1 = tok1 >> 8, t1 = tok1 & 255;
      Out[((b1 * 6 + (c >> 4)) * 256 + t1) * 16 + (c & 15)] = hi;
    }
  }
}

// Attention: one block per (b,h); one thread per query row; online softmax, f32x2.
__global__ void __launch_bounds__(256) attn_kernel() {
  int bh = blockIdx.x;
  __shared__ __align__(16) float ks[256][16];
  __shared__ __align__(16) float vs[256][16];
  const float* kb = g_k + bh * (256 * 16);
  const float* vb = g_v + bh * (256 * 16);
  for (int i = threadIdx.x; i < 1024; i += 256) {
    reinterpret_cast<float4*>(&ks[0][0])[i] = reinterpret_cast<const float4*>(kb)[i];
    reinterpret_cast<float4*>(&vs[0][0])[i] = reinterpret_cast<const float4*>(vb)[i];
  }
  __syncthreads();
  int t = threadIdx.x;
  const unsigned long long* qr =
      reinterpret_cast<const unsigned long long*>(g_q + (bh * 256 + t) * 16);
  unsigned long long q[8];
#pragma unroll
  for (int i = 0; i < 8; i++) q[i] = qr[i];
  float m = -1e30f, l = 0.0f;
  unsigned long long acc[8] = {};
  for (int s = 0; s <= t; s++) {
    const unsigned long long* kr = reinterpret_cast<const unsigned long long*>(ks[s]);
    unsigned long long d0 = mul2(q[0], kr[0]);
    unsigned long long d1 = mul2(q[1], kr[1]);
#pragma unroll
    for (int i = 2; i < 8; i += 2) {
      d0 = fma2(q[i],     kr[i],     d0);
      d1 = fma2(q[i + 1], kr[i + 1], d1);
    }
    float a0, a1, b0, b1;
    unpack2(d0, a0, a1); unpack2(d1, b0, b1);
    float dot = ((a0 + a1) + (b0 + b1)) * 0.25f;      // E^-0.5
    float mn   = fmaxf(m, dot);
    float corr = __expf(m - mn);
    float p    = __expf(dot - mn);
    l = l * corr + p;
    unsigned long long cd = f2x2(corr, corr);
    unsigned long long pd = f2x2(p, p);
    const unsigned long long* vr = reinterpret_cast<const unsigned long long*>(vs[s]);
#pragma unroll
    for (int i = 0; i < 8; i++) acc[i] = fma2(pd, vr[i], mul2(acc[i], cd));
    m = mn;
  }
  float inv = 1.0f / l;
  int b_ = bh / 6, h_ = bh % 6;
  float* orow = g_h + (b_ * 256 + t) * 96 + h_ * 16;
#pragma unroll
  for (int i = 0; i < 8; i++) {
    float lo, hi; unpack2(acc[i], lo, hi);
    orow[2 * i]     = lo * inv;
    orow[2 * i + 1] = hi * inv;
  }
}

// Projection + residual + noise1: x1 = x + o@Wp + bp + noise
__global__ void __launch_bounds__(256) proj_kernel(const float* __restrict__ Wp,
                                                   const float* __restrict__ bp,
                                                   const float* __restrict__ x,
                                                   unsigned nk0, unsigned nk1v) {
  GEMM_SMEM
  int row0 = blockIdx.x * 128;
  int tid = threadIdx.x;
  int cx = tid & 15, ry = tid >> 4;
  unsigned long long acc[4][6] = {};
  for (int k0 = 0; k0 < 96; k0 += 32) {
    GEMM_LOAD_A(g_h, 96)
#pragma unroll
    for (int i = 0; i < 12; i++) {
      int idx = tid + i * 256; int r = idx / 96, c = idx % 96;
      Bs[r][c] = Wp[(k0 + r) * 96 + c];
    }
    __syncthreads();
    GEMM_MAINLOOP
    __syncthreads();
  }
#pragma unroll
  for (int rp = 0; rp < 4; rp++) {
#pragma unroll
    for (int j = 0; j < 6; j++) {
      float lo, hi; unpack2(acc[rp][j], lo, hi);
      int c = cx * 6 + j;
      int tok0 = row0 + ry * 8 + 2 * rp;
      int i0 = tok0 * 96 + c, i1 = i0 + 96;
      g_x1[i0] = x[i0] + lo + bp[c] + jax_noise(nk0, nk1v, (unsigned)i0);
      g_x1[i1] = x[i1] + hi + bp[c] + jax_noise(nk0, nk1v, (unsigned)i1);
    }
  }
}

// FF1: relu(h2 @ W1 + b1) -> g_f  (blockIdx.y selects one of 4 col groups of 96)
__global__ void __launch_bounds__(256) ff1_kernel(const float* __restrict__ W1,
                                                  const float* __restrict__ b1) {
  GEMM_SMEM
  int row0 = blockIdx.x * 128;
  int co = blockIdx.y * 96;
  int tid = threadIdx.x;
  int cx = tid & 15, ry = tid >> 4;
  unsigned long long acc[4][6] = {};
  for (int k0 = 0; k0 < 96; k0 += 32) {
    GEMM_LOAD_A(g_h, 96)
#pragma unroll
    for (int i = 0; i < 12; i++) {
      int idx = tid + i * 256; int r = idx / 96, c = idx % 96;
      Bs[r][c] = W1[(k0 + r) * 384 + co + c];
    }
    __syncthreads();
    GEMM_MAINLOOP
    __syncthreads();
  }
#pragma unroll
  for (int rp = 0; rp < 4; rp++) {
#pragma unroll
    for (int j = 0; j < 6; j++) {
      float lo, hi; unpack2(acc[rp][j], lo, hi);
      int c = co + cx * 6 + j;
      int tok0 = row0 + ry * 8 + 2 * rp;
      float bb = b1[c];
      g_f[tok0 * 384 + c]       = fmaxf(lo + bb, 0.0f);
      g_f[(tok0 + 1) * 384 + c] = fmaxf(hi + bb, 0.0f);
    }
  }
}

// FF2 + residual + noise2 -> d_out
__global__ void __launch_bounds__(256) ff2_kernel(const float* __restrict__ W2,
                                                  const float* __restrict__ b2,
                                                  float* __restrict__ out,
                                                  unsigned nk0, unsigned nk1v) {
  GEMM_SMEM
  int row0 = blockIdx.x * 128;
  int tid = threadIdx.x;
  int cx = tid & 15, ry = tid >> 4;
  unsigned long long acc[4][6] = {};
  for (int k0 = 0; k0 < 384; k0 += 32) {
    GEMM_LOAD_A(g_f, 384)
#pragma unroll
    for (int i = 0; i < 12; i++) {
      int idx = tid + i * 256; int r = idx / 96, c = idx % 96;
      Bs[r][c] = W2[(k0 + r) * 96 + c];
    }
    __syncthreads();
    GEMM_MAINLOOP
    __syncthreads();
  }
#pragma unroll
  for (int rp = 0; rp < 4; rp++) {
#pragma unroll
    for (int j = 0; j < 6; j++) {
      float lo, hi; unpack2(acc[rp][j], lo, hi);
      int c = cx * 6 + j;
      int tok0 = row0 + ry * 8 + 2 * rp;
      int i0 = tok0 * 96 + c, i1 = i0 + 96;
      out[i0] = g_x1[i0] + lo + b2[c] + jax_noise(nk0, nk1v, (unsigned)i0);
      out[i1] = g_x1[i1] + hi + b2[c] + jax_noise(nk0, nk1v, (unsigned)i1);
    }
  }
}

extern "C" void kernel_launch(void* const* d_in, const int* in_sizes, int n_in,
                              void* d_out, int out_size) {
  (void)in_sizes; (void)n_in; (void)out_size;
  const float* x    = (const float*)d_in[0];
  const float* Wq   = (const float*)d_in[1];
  const float* Wk   = (const float*)d_in[2];
  const float* Wv   = (const float*)d_in[3];
  const float* Wp   = (const float*)d_in[4];
  const float* bp   = (const float*)d_in[5];
  const float* ln1g = (const float*)d_in[6];
  const float* ln1b = (const float*)d_in[7];
  const float* ln2g = (const float*)d_in[8];
  const float* ln2b = (const float*)d_in[9];
  const float* W1   = (const float*)d_in[10];
  const float* b1   = (const float*)d_in[11];
  const float* W2   = (const float*)d_in[12];
  const float* b2   = (const float*)d_in[13];
  float* out = (float*)d_out;

  unsigned nk1_0, nk1_1, nk2_0, nk2_1;
  tf2x32(0u, 42u, 0u, 0u, nk1_0, nk1_1);
  tf2x32(0u, 42u, 0u, 1u, nk2_0, nk2_1);

  ln_kernel  <<<8192, 256>>>(x, ln1g, ln1b);
  qkv_kernel <<<dim3(512, 3), 256>>>(Wq, Wk, Wv);
  attn_kernel<<<1536, 256>>>();
  proj_kernel<<<512, 256>>>(Wp, bp, x, nk1_0, nk1_1);
  ln_kernel  <<<8192, 256>>>(nullptr, ln2g, ln2b);
  ff1_kernel <<<dim3(512, 4), 256>>>(W1, b1);
  ff2_kernel <<<512, 256>>>(W2, b2, out, nk2_0, nk2_1);
}

// round 3
// speedup vs baseline: 1.7908x; 1.6480x over previous
#include <cuda_runtime.h>
#include <cstdint>

// Problem dims: B=256, T=256, D=96, H=6, E=16, DFF=384
#define NTOK 65536              // B*T

// ---------------- scratch (device globals; no allocations) ----------------
__device__ float g_h [NTOK * 96];    // LN output / attn concat output / LN2 out
__device__ float g_q [NTOK * 96];    // [B*H, T, E]
__device__ float g_k [NTOK * 96];
__device__ float g_v [NTOK * 96];
__device__ float g_x1[NTOK * 96];    // residual after attention branch
__device__ float g_f [NTOK * 384];   // FF hidden

// ---------------- packed f32x2 helpers (attention) ----------------
__device__ __forceinline__ unsigned long long f2x2(float lo, float hi) {
  unsigned long long r; asm("mov.b64 %0, {%1, %2};" : "=l"(r) : "f"(lo), "f"(hi)); return r;
}
__device__ __forceinline__ unsigned long long fma2(unsigned long long a, unsigned long long b, unsigned long long c) {
  unsigned long long d; asm("fma.rn.f32x2 %0, %1, %2, %3;" : "=l"(d) : "l"(a), "l"(b), "l"(c)); return d;
}
__device__ __forceinline__ unsigned long long mul2(unsigned long long a, unsigned long long b) {
  unsigned long long d; asm("mul.rn.f32x2 %0, %1, %2;" : "=l"(d) : "l"(a), "l"(b)); return d;
}
__device__ __forceinline__ void unpack2(unsigned long long v, float &lo, float &hi) {
  asm("mov.b64 {%0, %1}, %2;" : "=f"(lo), "=f"(hi) : "l"(v));
}

// ---------------- tf32 helpers ----------------
__device__ __forceinline__ float tf32r(float x) {
  unsigned r; asm("cvt.rna.tf32.f32 %0, %1;" : "=r"(r) : "f"(x)); return __uint_as_float(r);
}
__device__ __forceinline__ float4 tf32r4(float4 v) {
  v.x = tf32r(v.x); v.y = tf32r(v.y); v.z = tf32r(v.z); v.w = tf32r(v.w); return v;
}
__device__ __forceinline__ void mma_tf32(float (&d)[4], const unsigned (&a)[4], const unsigned (&b)[2]) {
  asm volatile("mma.sync.aligned.m16n8k8.row.col.f32.tf32.tf32.f32 "
               "{%0,%1,%2,%3}, {%4,%5,%6,%7}, {%8,%9}, {%0,%1,%2,%3};"
               : "+f"(d[0]), "+f"(d[1]), "+f"(d[2]), "+f"(d[3])
               : "r"(a[0]), "r"(a[1]), "r"(a[2]), "r"(a[3]), "r"(b[0]), "r"(b[1]));
}

// ---------------- JAX threefry-2x32 (20 rounds) ----------------
__host__ __device__ __forceinline__ void tf2x32(unsigned k0, unsigned k1,
                                                unsigned x0, unsigned x1,
                                                unsigned &o0, unsigned &o1) {
  unsigned k2 = k0 ^ k1 ^ 0x1BD11BDAu;
  unsigned v0 = x0 + k0, v1 = x1 + k1;
#define TFR(r) { v0 += v1; v1 = (v1 << (r)) | (v1 >> (32 - (r))); v1 ^= v0; }
  TFR(13) TFR(15) TFR(26) TFR(6)   v0 += k1; v1 += k2 + 1u;
  TFR(17) TFR(29) TFR(16) TFR(24)  v0 += k2; v1 += k0 + 2u;
  TFR(13) TFR(15) TFR(26) TFR(6)   v0 += k0; v1 += k1 + 3u;
  TFR(17) TFR(29) TFR(16) TFR(24)  v0 += k1; v1 += k2 + 4u;
  TFR(13) TFR(15) TFR(26) TFR(6)   v0 += k2; v1 += k0 + 5u;
#undef TFR
  o0 = v0; o1 = v1;
}

__device__ __forceinline__ float jax_noise(unsigned k0, unsigned k1, unsigned idx) {
  unsigned o0, o1;
  tf2x32(k0, k1, 0u, idx, o0, o1);
  unsigned bits = o0 ^ o1;
  float u = __uint_as_float((bits >> 9) | 0x3f800000u) - 1.0f;
  const float lo = -0.99999994f;
  float val = u * 1.99999994f + lo;
  val = fmaxf(lo, val);
  return 0.1f * (1.4142135381698608f * erfinvf(val));
}

// ---------------- LayerNorm: one warp per row of 96 ----------------
__global__ void __launch_bounds__(256) ln_kernel(const float* __restrict__ in,
                                                 const float* __restrict__ g,
                                                 const float* __restrict__ b) {
  const float* src = in ? in : g_x1;
  int row  = blockIdx.x * 8 + (threadIdx.x >> 5);
  int lane = threadIdx.x & 31;
  const float* xr = src + row * 96;
  float v0 = xr[lane], v1 = xr[lane + 32], v2 = xr[lane + 64];
  float s  = v0 + v1 + v2;
  float sq = v0 * v0 + v1 * v1 + v2 * v2;
#pragma unroll
  for (int o = 16; o; o >>= 1) {
    s  += __shfl_xor_sync(0xffffffffu, s, o);
    sq += __shfl_xor_sync(0xffffffffu, sq, o);
  }
  float m   = s * (1.0f / 96.0f);
  float var = sq * (1.0f / 96.0f) - m * m;
  float r   = rsqrtf(var + 1e-5f);
  float* out = g_h + row * 96;
  out[lane]      = (v0 - m) * r * g[lane]      + b[lane];
  out[lane + 32] = (v1 - m) * r * g[lane + 32] + b[lane + 32];
  out[lane + 64] = (v2 - m) * r * g[lane + 64] + b[lane + 64];
}

// ============ tf32 tensor-core GEMM: block 128x96, BK=48, 384 threads ============
// 12 warps = 4 row x 3 col; warp tile 32x32 = 2 (m16) x 4 (n8) mma tiles, K in steps of 8.
// As[row][k] pad 52 (A-frag reads hit 32 distinct banks); Bs[k][n] pad 104 (ditto).

#define GSMEM \
  __shared__ __align__(16) float As[128][52]; \
  __shared__ __align__(16) float Bs[48][104];

#define LOAD_A(SRC, LDK) \
  _Pragma("unroll") \
  for (int i = 0; i < 4; i++) { \
    int idx = tid + i * 384; int r = idx / 12, cq = idx % 12; \
    float4 v = *reinterpret_cast<const float4*>(&(SRC)[(size_t)(row0 + r) * (LDK) + k0 + cq * 4]); \
    *reinterpret_cast<float4*>(&As[r][cq * 4]) = tf32r4(v); \
  }

#define MMA_CHUNK \
  _Pragma("unroll") \
  for (int k8 = 0; k8 < 48; k8 += 8) { \
    unsigned a[2][4]; unsigned b[4][2]; \
    _Pragma("unroll") \
    for (int mt = 0; mt < 2; mt++) { \
      int m0 = wr * 32 + mt * 16 + gid; \
      a[mt][0] = __float_as_uint(As[m0][k8 + tig]); \
      a[mt][1] = __float_as_uint(As[m0 + 8][k8 + tig]); \
      a[mt][2] = __float_as_uint(As[m0][k8 + tig + 4]); \
      a[mt][3] = __float_as_uint(As[m0 + 8][k8 + tig + 4]); \
    } \
    _Pragma("unroll") \
    for (int nt = 0; nt < 4; nt++) { \
      int n0 = wc * 32 + nt * 8 + gid; \
      b[nt][0] = __float_as_uint(Bs[k8 + tig][n0]); \
      b[nt][1] = __float_as_uint(Bs[k8 + tig + 4][n0]); \
    } \
    _Pragma("unroll") \
    for (int mt = 0; mt < 2; mt++) \
      _Pragma("unroll") \
      for (int nt = 0; nt < 4; nt++) mma_tf32(acc[mt][nt], a[mt], b[nt]); \
  }

#define GEMM_PROLOG \
  int tid = threadIdx.x; \
  int warp = tid >> 5, lane = tid & 31; \
  int wr = warp / 3, wc = warp % 3; \
  int gid = lane >> 2, tig = lane & 3; \
  int row0 = blockIdx.x * 128; \
  float acc[2][4][4] = {};

// QKV: g_h[65536,96] @ W[h,d,e] -> out [B*H, T, E]
__global__ void __launch_bounds__(384, 2) qkv_kernel(const float* __restrict__ Wq,
                                                     const float* __restrict__ Wk,
                                                     const float* __restrict__ Wv) {
  const float* W   = (blockIdx.y == 0) ? Wq : (blockIdx.y == 1) ? Wk : Wv;
  float*       Out = (blockIdx.y == 0) ? g_q : (blockIdx.y == 1) ? g_k : g_v;
  GSMEM
  GEMM_PROLOG
  for (int k0 = 0; k0 < 96; k0 += 48) {
    LOAD_A(g_h, 96)
#pragma unroll
    for (int i = 0; i < 3; i++) {
      int idx = tid + i * 384; int r = idx / 24, c4 = idx % 24;
      int h = c4 / 4, e4 = c4 % 4;
      float4 v = *reinterpret_cast<const float4*>(&W[h * 1536 + (k0 + r) * 16 + e4 * 4]);
      *reinterpret_cast<float4*>(&Bs[r][c4 * 4]) = tf32r4(v);
    }
    __syncthreads();
    MMA_CHUNK
    __syncthreads();
  }
#pragma unroll
  for (int mt = 0; mt < 2; mt++) {
#pragma unroll
    for (int nt = 0; nt < 4; nt++) {
      int r0 = row0 + wr * 32 + mt * 16 + gid;
      int c0 = wc * 32 + nt * 8 + 2 * tig;
      int h = c0 >> 4, e = c0 & 15;
#pragma unroll
      for (int rr = 0; rr < 2; rr++) {
        int tok = r0 + rr * 8;
        int b_ = tok >> 8, t_ = tok & 255;
        float2 v = make_float2(acc[mt][nt][2 * rr], acc[mt][nt][2 * rr + 1]);
        *reinterpret_cast<float2*>(&Out[((b_ * 6 + h) * 256 + t_) * 16 + e]) = v;
      }
    }
  }
}

// Projection + residual + noise1
__global__ void __launch_bounds__(384, 2) proj_kernel(const float* __restrict__ Wp,
                                                      const float* __restrict__ bp,
                                                      const float* __restrict__ x,
                                                      unsigned nk0, unsigned nk1v) {
  GSMEM
  GEMM_PROLOG
  for (int k0 = 0; k0 < 96; k0 += 48) {
    LOAD_A(g_h, 96)
#pragma unroll
    for (int i = 0; i < 3; i++) {
      int idx = tid + i * 384; int r = idx / 24, c4 = idx % 24;
      float4 v = *reinterpret_cast<const float4*>(&Wp[(k0 + r) * 96 + c4 * 4]);
      *reinterpret_cast<float4*>(&Bs[r][c4 * 4]) = tf32r4(v);
    }
    __syncthreads();
    MMA_CHUNK
    __syncthreads();
  }
#pragma unroll
  for (int mt = 0; mt < 2; mt++) {
#pragma unroll
    for (int nt = 0; nt < 4; nt++) {
      int r0 = row0 + wr * 32 + mt * 16 + gid;
      int c0 = wc * 32 + nt * 8 + 2 * tig;
      float bp0 = bp[c0], bp1 = bp[c0 + 1];
#pragma unroll
      for (int rr = 0; rr < 2; rr++) {
        int tok = r0 + rr * 8;
        int i0 = tok * 96 + c0;
        float o0 = x[i0]     + acc[mt][nt][2 * rr]     + bp0 + jax_noise(nk0, nk1v, (unsigned)i0);
        float o1 = x[i0 + 1] + acc[mt][nt][2 * rr + 1] + bp1 + jax_noise(nk0, nk1v, (unsigned)(i0 + 1));
        *reinterpret_cast<float2*>(&g_x1[i0]) = make_float2(o0, o1);
      }
    }
  }
}

// FF1: relu(h2 @ W1 + b1) -> g_f  (blockIdx.y = col group of 96)
__global__ void __launch_bounds__(384, 2) ff1_kernel(const float* __restrict__ W1,
                                                     const float* __restrict__ b1) {
  GSMEM
  GEMM_PROLOG
  int co = blockIdx.y * 96;
  for (int k0 = 0; k0 < 96; k0 += 48) {
    LOAD_A(g_h, 96)
#pragma unroll
    for (int i = 0; i < 3; i++) {
      int idx = tid + i * 384; int r = idx / 24, c4 = idx % 24;
      float4 v = *reinterpret_cast<const float4*>(&W1[(k0 + r) * 384 + co + c4 * 4]);
      *reinterpret_cast<float4*>(&Bs[r][c4 * 4]) = tf32r4(v);
    }
    __syncthreads();
    MMA_CHUNK
    __syncthreads();
  }
#pragma unroll
  for (int mt = 0; mt < 2; mt++) {
#pragma unroll
    for (int nt = 0; nt < 4; nt++) {
      int r0 = row0 + wr * 32 + mt * 16 + gid;
      int c0 = wc * 32 + nt * 8 + 2 * tig;
      float b0 = b1[co + c0], b1v = b1[co + c0 + 1];
#pragma unroll
      for (int rr = 0; rr < 2; rr++) {
        int tok = r0 + rr * 8;
        float2 v = make_float2(fmaxf(acc[mt][nt][2 * rr] + b0, 0.0f),
                               fmaxf(acc[mt][nt][2 * rr + 1] + b1v, 0.0f));
        *reinterpret_cast<float2*>(&g_f[tok * 384 + co + c0]) = v;
      }
    }
  }
}

// FF2 + residual + noise2 -> d_out  (K = 384, 8 chunks)
__global__ void __launch_bounds__(384, 2) ff2_kernel(const float* __restrict__ W2,
                                                     const float* __restrict__ b2,
                                                     float* __restrict__ out,
                                                     unsigned nk0, unsigned nk1v) {
  GSMEM
  GEMM_PROLOG
  for (int k0 = 0; k0 < 384; k0 += 48) {
    LOAD_A(g_f, 384)
#pragma unroll
    for (int i = 0; i < 3; i++) {
      int idx = tid + i * 384; int r = idx / 24, c4 = idx % 24;
      float4 v = *reinterpret_cast<const float4*>(&W2[(k0 + r) * 96 + c4 * 4]);
      *reinterpret_cast<float4*>(&Bs[r][c4 * 4]) = tf32r4(v);
    }
    __syncthreads();
    MMA_CHUNK
    __syncthreads();
  }
#pragma unroll
  for (int mt = 0; mt < 2; mt++) {
#pragma unroll
    for (int nt = 0; nt < 4; nt++) {
      int r0 = row0 + wr * 32 + mt * 16 + gid;
      int c0 = wc * 32 + nt * 8 + 2 * tig;
      float bb0 = b2[c0], bb1 = b2[c0 + 1];
#pragma unroll
      for (int rr = 0; rr < 2; rr++) {
        int tok = r0 + rr * 8;
        int i0 = tok * 96 + c0;
        float o0 = g_x1[i0]     + acc[mt][nt][2 * rr]     + bb0 + jax_noise(nk0, nk1v, (unsigned)i0);
        float o1 = g_x1[i0 + 1] + acc[mt][nt][2 * rr + 1] + bb1 + jax_noise(nk0, nk1v, (unsigned)(i0 + 1));
        *reinterpret_cast<float2*>(&out[i0]) = make_float2(o0, o1);
      }
    }
  }
}

// Attention: one block per (b,h); one thread per query row; online softmax, f32x2.
__global__ void __launch_bounds__(256) attn_kernel() {
  int bh = blockIdx.x;
  __shared__ __align__(16) float ks[256][16];
  __shared__ __align__(16) float vs[256][16];
  const float* kb = g_k + bh * (256 * 16);
  const float* vb = g_v + bh * (256 * 16);
  for (int i = threadIdx.x; i < 1024; i += 256) {
    reinterpret_cast<float4*>(&ks[0][0])[i] = reinterpret_cast<const float4*>(kb)[i];
    reinterpret_cast<float4*>(&vs[0][0])[i] = reinterpret_cast<const float4*>(vb)[i];
  }
  __syncthreads();
  int t = threadIdx.x;
  const unsigned long long* qr =
      reinterpret_cast<const unsigned long long*>(g_q + (bh * 256 + t) * 16);
  unsigned long long q[8];
#pragma unroll
  for (int i = 0; i < 8; i++) q[i] = qr[i];
  float m = -1e30f, l = 0.0f;
  unsigned long long acc[8] = {};
  for (int s = 0; s <= t; s++) {
    const unsigned long long* kr = reinterpret_cast<const unsigned long long*>(ks[s]);
    unsigned long long d0 = mul2(q[0], kr[0]);
    unsigned long long d1 = mul2(q[1], kr[1]);
#pragma unroll
    for (int i = 2; i < 8; i += 2) {
      d0 = fma2(q[i],     kr[i],     d0);
      d1 = fma2(q[i + 1], kr[i + 1], d1);
    }
    float a0, a1, b0, b1;
    unpack2(d0, a0, a1); unpack2(d1, b0, b1);
    float dot = ((a0 + a1) + (b0 + b1)) * 0.25f;
    float mn   = fmaxf(m, dot);
    float corr = __expf(m - mn);
    float p    = __expf(dot - mn);
    l = l * corr + p;
    unsigned long long cd = f2x2(corr, corr);
    unsigned long long pd = f2x2(p, p);
    const unsigned long long* vr = reinterpret_cast<const unsigned long long*>(vs[s]);
#pragma unroll
    for (int i = 0; i < 8; i++) acc[i] = fma2(pd, vr[i], mul2(acc[i], cd));
    m = mn;
  }
  float inv = 1.0f / l;
  int b_ = bh / 6, h_ = bh % 6;
  float* orow = g_h + (b_ * 256 + t) * 96 + h_ * 16;
#pragma unroll
  for (int i = 0; i < 8; i++) {
    float lo, hi; unpack2(acc[i], lo, hi);
    orow[2 * i]     = lo * inv;
    orow[2 * i + 1] = hi * inv;
  }
}

extern "C" void kernel_launch(void* const* d_in, const int* in_sizes, int n_in,
                              void* d_out, int out_size) {
  (void)in_sizes; (void)n_in; (void)out_size;
  const float* x    = (const float*)d_in[0];
  const float* Wq   = (const float*)d_in[1];
  const float* Wk   = (const float*)d_in[2];
  const float* Wv   = (const float*)d_in[3];
  const float* Wp   = (const float*)d_in[4];
  const float* bp   = (const float*)d_in[5];
  const float* ln1g = (const float*)d_in[6];
  const float* ln1b = (const float*)d_in[7];
  const float* ln2g = (const float*)d_in[8];
  const float* ln2b = (const float*)d_in[9];
  const float* W1   = (const float*)d_in[10];
  const float* b1   = (const float*)d_in[11];
  const float* W2   = (const float*)d_in[12];
  const float* b2   = (const float*)d_in[13];
  float* out = (float*)d_out;

  unsigned nk1_0, nk1_1, nk2_0, nk2_1;
  tf2x32(0u, 42u, 0u, 0u, nk1_0, nk1_1);
  tf2x32(0u, 42u, 0u, 1u, nk2_0, nk2_1);

  ln_kernel  <<<8192, 256>>>(x, ln1g, ln1b);
  qkv_kernel <<<dim3(512, 3), 384>>>(Wq, Wk, Wv);
  attn_kernel<<<1536, 256>>>();
  proj_kernel<<<512, 384>>>(Wp, bp, x, nk1_0, nk1_1);
  ln_kernel  <<<8192, 256>>>(nullptr, ln2g, ln2b);
  ff1_kernel <<<dim3(512, 4), 384>>>(W1, b1);
  ff2_kernel <<<512, 384>>>(W2, b2, out, nk2_0, nk2_1);
}

// round 4
// speedup vs baseline: 1.9023x; 1.0623x over previous
#include <cuda_runtime.h>
#include <cstdint>

// Problem dims: B=256, T=256, D=96, H=6, E=16, DFF=384
#define NTOK 65536              // B*T

// ---------------- scratch (device globals; no allocations) ----------------
__device__ float g_h [NTOK * 96];    // attn concat output
__device__ float g_q [NTOK * 96];    // [B*H, T, E]
__device__ float g_k [NTOK * 96];
__device__ float g_v [NTOK * 96];
__device__ float g_x1[NTOK * 96];    // residual after attention branch
__device__ float g_f [NTOK * 384];   // FF hidden

// ---------------- packed f32x2 helpers (attention) ----------------
__device__ __forceinline__ unsigned long long f2x2(float lo, float hi) {
  unsigned long long r; asm("mov.b64 %0, {%1, %2};" : "=l"(r) : "f"(lo), "f"(hi)); return r;
}
__device__ __forceinline__ unsigned long long fma2(unsigned long long a, unsigned long long b, unsigned long long c) {
  unsigned long long d; asm("fma.rn.f32x2 %0, %1, %2, %3;" : "=l"(d) : "l"(a), "l"(b), "l"(c)); return d;
}
__device__ __forceinline__ unsigned long long mul2(unsigned long long a, unsigned long long b) {
  unsigned long long d; asm("mul.rn.f32x2 %0, %1, %2;" : "=l"(d) : "l"(a), "l"(b)); return d;
}
__device__ __forceinline__ void unpack2(unsigned long long v, float &lo, float &hi) {
  asm("mov.b64 {%0, %1}, %2;" : "=f"(lo), "=f"(hi) : "l"(v));
}

// ---------------- tf32 helpers ----------------
__device__ __forceinline__ float tf32r(float x) {
  unsigned r; asm("cvt.rna.tf32.f32 %0, %1;" : "=r"(r) : "f"(x)); return __uint_as_float(r);
}
__device__ __forceinline__ float4 tf32r4(float4 v) {
  v.x = tf32r(v.x); v.y = tf32r(v.y); v.z = tf32r(v.z); v.w = tf32r(v.w); return v;
}
__device__ __forceinline__ void mma_tf32(float (&d)[4], const unsigned (&a)[4], const unsigned (&b)[2]) {
  asm volatile("mma.sync.aligned.m16n8k8.row.col.f32.tf32.tf32.f32 "
               "{%0,%1,%2,%3}, {%4,%5,%6,%7}, {%8,%9}, {%0,%1,%2,%3};"
               : "+f"(d[0]), "+f"(d[1]), "+f"(d[2]), "+f"(d[3])
               : "r"(a[0]), "r"(a[1]), "r"(a[2]), "r"(a[3]), "r"(b[0]), "r"(b[1]));
}

// ---------------- JAX threefry-2x32 (20 rounds) ----------------
__host__ __device__ __forceinline__ void tf2x32(unsigned k0, unsigned k1,
                                                unsigned x0, unsigned x1,
                                                unsigned &o0, unsigned &o1) {
  unsigned k2 = k0 ^ k1 ^ 0x1BD11BDAu;
  unsigned v0 = x0 + k0, v1 = x1 + k1;
#define TFR(r) { v0 += v1; v1 = (v1 << (r)) | (v1 >> (32 - (r))); v1 ^= v0; }
  TFR(13) TFR(15) TFR(26) TFR(6)   v0 += k1; v1 += k2 + 1u;
  TFR(17) TFR(29) TFR(16) TFR(24)  v0 += k2; v1 += k0 + 2u;
  TFR(13) TFR(15) TFR(26) TFR(6)   v0 += k0; v1 += k1 + 3u;
  TFR(17) TFR(29) TFR(16) TFR(24)  v0 += k1; v1 += k2 + 4u;
  TFR(13) TFR(15) TFR(26) TFR(6)   v0 += k2; v1 += k0 + 5u;
#undef TFR
  o0 = v0; o1 = v1;
}

__device__ __forceinline__ float jax_noise(unsigned k0, unsigned k1, unsigned idx) {
  unsigned o0, o1;
  tf2x32(k0, k1, 0u, idx, o0, o1);
  unsigned bits = o0 ^ o1;
  float u = __uint_as_float((bits >> 9) | 0x3f800000u) - 1.0f;
  const float lo = -0.99999994f;
  float val = u * 1.99999994f + lo;
  val = fmaxf(lo, val);
  return 0.1f * (1.4142135381698608f * erfinvf(val));
}

// ============ shared-memory layout for GEMM kernels (dynamic, 91136 B) ============
// A tile: 128 rows x 96 cols, stride 100 (=4 mod 32 -> conflict-free mma frags)
// B tile: 96 k x 96 n, stride 104 (=8 mod 32 -> conflict-free b frags)
#define SA(r, c) sm[(r) * 100 + (c)]
#define SB(r, c) sm[12800 + (r) * 104 + (c)]
#define SMEM_BYTES ((12800 + 96 * 104) * 4)

#define GEMM_PROLOG \
  extern __shared__ float sm[]; \
  int tid = threadIdx.x; \
  int warp = tid >> 5, lane = tid & 31; \
  int wr = warp >> 2, wc = warp & 3;          /* dummy, overwritten below */ \
  wr = warp / 3; wc = warp % 3; \
  int gid = lane >> 2, tig = lane & 3; \
  int row0 = blockIdx.x * 128;

// Load A tile (tf32-rounded) from SRC with row stride LDK, k offset K0.
#define LOAD_A_TF32(SRC, LDK, K0) \
  _Pragma("unroll") \
  for (int i = 0; i < 8; i++) { \
    int idx = tid + i * 384; int r = idx / 24, c4 = idx % 24; \
    float4 v = *reinterpret_cast<const float4*>(&(SRC)[(size_t)(row0 + r) * (LDK) + (K0) + c4 * 4]); \
    *reinterpret_cast<float4*>(&SA(r, c4 * 4)) = tf32r4(v); \
  }

// Load A tile RAW (for LN-fused kernels)
#define LOAD_A_RAW(SRC) \
  _Pragma("unroll") \
  for (int i = 0; i < 8; i++) { \
    int idx = tid + i * 384; int r = idx / 24, c4 = idx % 24; \
    *reinterpret_cast<float4*>(&SA(r, c4 * 4)) = \
        *reinterpret_cast<const float4*>(&(SRC)[(size_t)(row0 + r) * 96 + c4 * 4]); \
  }

// In-smem LayerNorm over the 128x96 A tile; writes back tf32-rounded.
#define LN_SMEM(G, Bv) \
  { \
    float g0 = (G)[lane], g1 = (G)[lane + 32], g2 = (G)[lane + 64]; \
    float b0 = (Bv)[lane], b1 = (Bv)[lane + 32], b2 = (Bv)[lane + 64]; \
    for (int r = warp; r < 128; r += 12) { \
      float v0 = SA(r, lane), v1 = SA(r, lane + 32), v2 = SA(r, lane + 64); \
      float s = v0 + v1 + v2, sq = v0 * v0 + v1 * v1 + v2 * v2; \
      _Pragma("unroll") \
      for (int o = 16; o; o >>= 1) { \
        s  += __shfl_xor_sync(0xffffffffu, s, o); \
        sq += __shfl_xor_sync(0xffffffffu, sq, o); \
      } \
      float mu = s * (1.0f / 96.0f); \
      float rs = rsqrtf(sq * (1.0f / 96.0f) - mu * mu + 1e-5f); \
      SA(r, lane)      = tf32r((v0 - mu) * rs * g0 + b0); \
      SA(r, lane + 32) = tf32r((v1 - mu) * rs * g1 + b1); \
      SA(r, lane + 64) = tf32r((v2 - mu) * rs * g2 + b2); \
    } \
  }

// Full K=96 MMA accumulate into acc[2][4][4]
#define MMA_K96 \
  _Pragma("unroll") \
  for (int k8 = 0; k8 < 96; k8 += 8) { \
    unsigned a[2][4]; unsigned b[4][2]; \
    _Pragma("unroll") \
    for (int mt = 0; mt < 2; mt++) { \
      int m0 = wr * 32 + mt * 16 + gid; \
      a[mt][0] = __float_as_uint(SA(m0,     k8 + tig)); \
      a[mt][1] = __float_as_uint(SA(m0 + 8, k8 + tig)); \
      a[mt][2] = __float_as_uint(SA(m0,     k8 + tig + 4)); \
      a[mt][3] = __float_as_uint(SA(m0 + 8, k8 + tig + 4)); \
    } \
    _Pragma("unroll") \
    for (int nt = 0; nt < 4; nt++) { \
      int n0 = wc * 32 + nt * 8 + gid; \
      b[nt][0] = __float_as_uint(SB(k8 + tig,     n0)); \
      b[nt][1] = __float_as_uint(SB(k8 + tig + 4, n0)); \
    } \
    _Pragma("unroll") \
    for (int mt = 0; mt < 2; mt++) \
      _Pragma("unroll") \
      for (int nt = 0; nt < 4; nt++) mma_tf32(acc[mt][nt], a[mt], b[nt]); \
  }

// ---- fused LN1 + QKV: x -> LN -> 3 GEMMs (A tile resident) ----
__global__ void __launch_bounds__(384, 2) qkv_kernel(const float* __restrict__ x,
                                                     const float* __restrict__ ln1g,
                                                     const float* __restrict__ ln1b,
                                                     const float* __restrict__ Wq,
                                                     const float* __restrict__ Wk,
                                                     const float* __restrict__ Wv) {
  GEMM_PROLOG
  LOAD_A_RAW(x)
  __syncthreads();
  LN_SMEM(ln1g, ln1b)
  for (int w = 0; w < 3; w++) {
    const float* W   = (w == 0) ? Wq : (w == 1) ? Wk : Wv;
    float*       Out = (w == 0) ? g_q : (w == 1) ? g_k : g_v;
    __syncthreads();                              // prior MMA / LN writeback done
#pragma unroll
    for (int i = 0; i < 6; i++) {                 // B: 96x96 from W[h,d,e]
      int idx = tid + i * 384; int r = idx / 24, c4 = idx % 24;
      int h = c4 >> 2, e4 = c4 & 3;
      float4 v = *reinterpret_cast<const float4*>(&W[h * 1536 + r * 16 + e4 * 4]);
      *reinterpret_cast<float4*>(&SB(r, c4 * 4)) = tf32r4(v);
    }
    __syncthreads();
    float acc[2][4][4] = {};
    MMA_K96
#pragma unroll
    for (int mt = 0; mt < 2; mt++)
#pragma unroll
      for (int nt = 0; nt < 4; nt++) {
        int r0 = row0 + wr * 32 + mt * 16 + gid;
        int c0 = wc * 32 + nt * 8 + 2 * tig;
        int h = c0 >> 4, e = c0 & 15;
#pragma unroll
        for (int rr = 0; rr < 2; rr++) {
          int tok = r0 + rr * 8;
          int b_ = tok >> 8, t_ = tok & 255;
          *reinterpret_cast<float2*>(&Out[((b_ * 6 + h) * 256 + t_) * 16 + e]) =
              make_float2(acc[mt][nt][2 * rr], acc[mt][nt][2 * rr + 1]);
        }
      }
  }
}

// ---- attention: no-max softmax (scores tiny; shift-invariant) ----
__global__ void __launch_bounds__(256) attn_kernel() {
  int bh = blockIdx.x;
  __shared__ __align__(16) float ks[256][16];
  __shared__ __align__(16) float vs[256][16];
  const float* kb = g_k + bh * (256 * 16);
  const float* vb = g_v + bh * (256 * 16);
  for (int i = threadIdx.x; i < 1024; i += 256) {
    reinterpret_cast<float4*>(&ks[0][0])[i] = reinterpret_cast<const float4*>(kb)[i];
    reinterpret_cast<float4*>(&vs[0][0])[i] = reinterpret_cast<const float4*>(vb)[i];
  }
  __syncthreads();
  int t = threadIdx.x;
  const unsigned long long* qr =
      reinterpret_cast<const unsigned long long*>(g_q + (bh * 256 + t) * 16);
  unsigned long long q[8];
#pragma unroll
  for (int i = 0; i < 8; i++) q[i] = qr[i];
  float l = 0.0f;
  unsigned long long acc[8] = {};
  for (int s = 0; s <= t; s++) {
    const unsigned long long* kr = reinterpret_cast<const unsigned long long*>(ks[s]);
    unsigned long long d0 = mul2(q[0], kr[0]);
    unsigned long long d1 = mul2(q[1], kr[1]);
#pragma unroll
    for (int i = 2; i < 8; i += 2) {
      d0 = fma2(q[i],     kr[i],     d0);
      d1 = fma2(q[i + 1], kr[i + 1], d1);
    }
    float a0, a1, b0, b1;
    unpack2(d0, a0, a1); unpack2(d1, b0, b1);
    float p = __expf(((a0 + a1) + (b0 + b1)) * 0.25f);
    l += p;
    unsigned long long pd = f2x2(p, p);
    const unsigned long long* vr = reinterpret_cast<const unsigned long long*>(vs[s]);
#pragma unroll
    for (int i = 0; i < 8; i++) acc[i] = fma2(pd, vr[i], acc[i]);
  }
  float inv = 1.0f / l;
  int b_ = bh / 6, h_ = bh % 6;
  float* orow = g_h + (b_ * 256 + t) * 96 + h_ * 16;
#pragma unroll
  for (int i = 0; i < 8; i++) {
    float lo, hi; unpack2(acc[i], lo, hi);
    orow[2 * i]     = lo * inv;
    orow[2 * i + 1] = hi * inv;
  }
}

// ---- projection + residual + noise1 ----
__global__ void __launch_bounds__(384, 2) proj_kernel(const float* __restrict__ Wp,
                                                      const float* __restrict__ bp,
                                                      const float* __restrict__ x,
                                                      unsigned nk0, unsigned nk1v) {
  GEMM_PROLOG
  LOAD_A_TF32(g_h, 96, 0)
#pragma unroll
  for (int i = 0; i < 6; i++) {
    int idx = tid + i * 384; int r = idx / 24, c4 = idx % 24;
    float4 v = *reinterpret_cast<const float4*>(&Wp[r * 96 + c4 * 4]);
    *reinterpret_cast<float4*>(&SB(r, c4 * 4)) = tf32r4(v);
  }
  __syncthreads();
  float acc[2][4][4] = {};
  MMA_K96
#pragma unroll
  for (int mt = 0; mt < 2; mt++)
#pragma unroll
    for (int nt = 0; nt < 4; nt++) {
      int r0 = row0 + wr * 32 + mt * 16 + gid;
      int c0 = wc * 32 + nt * 8 + 2 * tig;
      float bp0 = bp[c0], bp1 = bp[c0 + 1];
#pragma unroll
      for (int rr = 0; rr < 2; rr++) {
        int i0 = (r0 + rr * 8) * 96 + c0;
        float o0 = x[i0]     + acc[mt][nt][2 * rr]     + bp0 + jax_noise(nk0, nk1v, (unsigned)i0);
        float o1 = x[i0 + 1] + acc[mt][nt][2 * rr + 1] + bp1 + jax_noise(nk0, nk1v, (unsigned)(i0 + 1));
        *reinterpret_cast<float2*>(&g_x1[i0]) = make_float2(o0, o1);
      }
    }
}

// ---- fused LN2 + FF1: g_x1 -> LN -> 4 col-group GEMMs + relu ----
__global__ void __launch_bounds__(384, 2) ff1_kernel(const float* __restrict__ W1,
                                                     const float* __restrict__ b1,
                                                     const float* __restrict__ ln2g,
                                                     const float* __restrict__ ln2b) {
  GEMM_PROLOG
  LOAD_A_RAW(g_x1)
  __syncthreads();
  LN_SMEM(ln2g, ln2b)
  for (int grp = 0; grp < 4; grp++) {
    int co = grp * 96;
    __syncthreads();
#pragma unroll
    for (int i = 0; i < 6; i++) {
      int idx = tid + i * 384; int r = idx / 24, c4 = idx % 24;
      float4 v = *reinterpret_cast<const float4*>(&W1[r * 384 + co + c4 * 4]);
      *reinterpret_cast<float4*>(&SB(r, c4 * 4)) = tf32r4(v);
    }
    __syncthreads();
    float acc[2][4][4] = {};
    MMA_K96
#pragma unroll
    for (int mt = 0; mt < 2; mt++)
#pragma unroll
      for (int nt = 0; nt < 4; nt++) {
        int r0 = row0 + wr * 32 + mt * 16 + gid;
        int c0 = wc * 32 + nt * 8 + 2 * tig;
        float bb0 = b1[co + c0], bb1 = b1[co + c0 + 1];
#pragma unroll
        for (int rr = 0; rr < 2; rr++) {
          int tok = r0 + rr * 8;
          *reinterpret_cast<float2*>(&g_f[(size_t)tok * 384 + co + c0]) =
              make_float2(fmaxf(acc[mt][nt][2 * rr] + bb0, 0.0f),
                          fmaxf(acc[mt][nt][2 * rr + 1] + bb1, 0.0f));
        }
      }
  }
}

// ---- FF2 + residual + noise2 -> out (K=384 in 4 chunks) ----
__global__ void __launch_bounds__(384, 2) ff2_kernel(const float* __restrict__ W2,
                                                     const float* __restrict__ b2,
                                                     float* __restrict__ out,
                                                     unsigned nk0, unsigned nk1v) {
  GEMM_PROLOG
  float acc[2][4][4] = {};
  for (int kc = 0; kc < 4; kc++) {
    int k0 = kc * 96;
    __syncthreads();
    LOAD_A_TF32(g_f, 384, k0)
#pragma unroll
    for (int i = 0; i < 6; i++) {
      int idx = tid + i * 384; int r = idx / 24, c4 = idx % 24;
      float4 v = *reinterpret_cast<const float4*>(&W2[(k0 + r) * 96 + c4 * 4]);
      *reinterpret_cast<float4*>(&SB(r, c4 * 4)) = tf32r4(v);
    }
    __syncthreads();
    MMA_K96
  }
#pragma unroll
  for (int mt = 0; mt < 2; mt++)
#pragma unroll
    for (int nt = 0; nt < 4; nt++) {
      int r0 = row0 + wr * 32 + mt * 16 + gid;
      int c0 = wc * 32 + nt * 8 + 2 * tig;
      float bb0 = b2[c0], bb1 = b2[c0 + 1];
#pragma unroll
      for (int rr = 0; rr < 2; rr++) {
        int i0 = (r0 + rr * 8) * 96 + c0;
        float o0 = g_x1[i0]     + acc[mt][nt][2 * rr]     + bb0 + jax_noise(nk0, nk1v, (unsigned)i0);
        float o1 = g_x1[i0 + 1] + acc[mt][nt][2 * rr + 1] + bb1 + jax_noise(nk0, nk1v, (unsigned)(i0 + 1));
        *reinterpret_cast<float2*>(&out[i0]) = make_float2(o0, o1);
      }
    }
}

extern "C" void kernel_launch(void* const* d_in, const int* in_sizes, int n_in,
                              void* d_out, int out_size) {
  (void)in_sizes; (void)n_in; (void)out_size;
  const float* x    = (const float*)d_in[0];
  const float* Wq   = (const float*)d_in[1];
  const float* Wk   = (const float*)d_in[2];
  const float* Wv   = (const float*)d_in[3];
  const float* Wp   = (const float*)d_in[4];
  const float* bp   = (const float*)d_in[5];
  const float* ln1g = (const float*)d_in[6];
  const float* ln1b = (const float*)d_in[7];
  const float* ln2g = (const float*)d_in[8];
  const float* ln2b = (const float*)d_in[9];
  const float* W1   = (const float*)d_in[10];
  const float* b1   = (const float*)d_in[11];
  const float* W2   = (const float*)d_in[12];
  const float* b2   = (const float*)d_in[13];
  float* out = (float*)d_out;

  unsigned nk1_0, nk1_1, nk2_0, nk2_1;
  tf2x32(0u, 42u, 0u, 0u, nk1_0, nk1_1);
  tf2x32(0u, 42u, 0u, 1u, nk2_0, nk2_1);

  cudaFuncSetAttribute(qkv_kernel,  cudaFuncAttributeMaxDynamicSharedMemorySize, SMEM_BYTES);
  cudaFuncSetAttribute(proj_kernel, cudaFuncAttributeMaxDynamicSharedMemorySize, SMEM_BYTES);
  cudaFuncSetAttribute(ff1_kernel,  cudaFuncAttributeMaxDynamicSharedMemorySize, SMEM_BYTES);
  cudaFuncSetAttribute(ff2_kernel,  cudaFuncAttributeMaxDynamicSharedMemorySize, SMEM_BYTES);

  qkv_kernel <<<512, 384, SMEM_BYTES>>>(x, ln1g, ln1b, Wq, Wk, Wv);
  attn_kernel<<<1536, 256>>>();
  proj_kernel<<<512, 384, SMEM_BYTES>>>(Wp, bp, x, nk1_0, nk1_1);
  ff1_kernel <<<512, 384, SMEM_BYTES>>>(W1, b1, ln2g, ln2b);
  ff2_kernel <<<512, 384, SMEM_BYTES>>>(W2, b2, out, nk2_0, nk2_1);
}

// round 5
// speedup vs baseline: 2.3260x; 1.2227x over previous
#include <cuda_runtime.h>
#include <cuda_bf16.h>
#include <cstdint>

// Problem dims: B=256, T=256, D=96, H=6, E=16, DFF=384
#define NTOK 65536              // B*T

// ---------------- scratch (device globals; no allocations) ----------------
__device__ __nv_bfloat16 g_h [NTOK * 96];    // attn concat output (bf16)
__device__ float         g_q [NTOK * 96];    // [B*H, T, E] fp32
__device__ float         g_k [NTOK * 96];
__device__ float         g_v [NTOK * 96];
__device__ float         g_x1[NTOK * 96];    // residual after attention branch
__device__ __nv_bfloat16 g_f [NTOK * 384];   // FF hidden (bf16)

// ---------------- packed f32x2 helpers (attention) ----------------
__device__ __forceinline__ unsigned long long f2x2(float lo, float hi) {
  unsigned long long r; asm("mov.b64 %0, {%1, %2};" : "=l"(r) : "f"(lo), "f"(hi)); return r;
}
__device__ __forceinline__ unsigned long long fma2(unsigned long long a, unsigned long long b, unsigned long long c) {
  unsigned long long d; asm("fma.rn.f32x2 %0, %1, %2, %3;" : "=l"(d) : "l"(a), "l"(b), "l"(c)); return d;
}
__device__ __forceinline__ unsigned long long mul2(unsigned long long a, unsigned long long b) {
  unsigned long long d; asm("mul.rn.f32x2 %0, %1, %2;" : "=l"(d) : "l"(a), "l"(b)); return d;
}
__device__ __forceinline__ void unpack2(unsigned long long v, float &lo, float &hi) {
  asm("mov.b64 {%0, %1}, %2;" : "=f"(lo), "=f"(hi) : "l"(v));
}

// ---------------- bf16 mma + ldmatrix helpers ----------------
__device__ __forceinline__ void ldsm4(unsigned (&r)[4], unsigned addr) {
  asm volatile("ldmatrix.sync.aligned.m8n8.x4.shared.b16 {%0,%1,%2,%3}, [%4];"
               : "=r"(r[0]), "=r"(r[1]), "=r"(r[2]), "=r"(r[3]) : "r"(addr));
}
__device__ __forceinline__ void ldsm4t(unsigned (&r)[4], unsigned addr) {
  asm volatile("ldmatrix.sync.aligned.m8n8.x4.trans.shared.b16 {%0,%1,%2,%3}, [%4];"
               : "=r"(r[0]), "=r"(r[1]), "=r"(r[2]), "=r"(r[3]) : "r"(addr));
}
__device__ __forceinline__ void mma_bf16(float (&d)[4], const unsigned (&a)[4], unsigned b0, unsigned b1) {
  asm volatile("mma.sync.aligned.m16n8k16.row.col.f32.bf16.bf16.f32 "
               "{%0,%1,%2,%3}, {%4,%5,%6,%7}, {%8,%9}, {%0,%1,%2,%3};"
               : "+f"(d[0]), "+f"(d[1]), "+f"(d[2]), "+f"(d[3])
               : "r"(a[0]), "r"(a[1]), "r"(a[2]), "r"(a[3]), "r"(b0), "r"(b1));
}
__device__ __forceinline__ unsigned s2u(const void* p) {
  return (unsigned)__cvta_generic_to_shared(p);
}
__device__ __forceinline__ unsigned pack_bf2(float lo, float hi) {
  __nv_bfloat162 h = __float22bfloat162_rn(make_float2(lo, hi));
  return *reinterpret_cast<unsigned*>(&h);
}

// ---------------- JAX threefry-2x32 (20 rounds) ----------------
__host__ __device__ __forceinline__ void tf2x32(unsigned k0, unsigned k1,
                                                unsigned x0, unsigned x1,
                                                unsigned &o0, unsigned &o1) {
  unsigned k2 = k0 ^ k1 ^ 0x1BD11BDAu;
  unsigned v0 = x0 + k0, v1 = x1 + k1;
#define TFR(r) { v0 += v1; v1 = (v1 << (r)) | (v1 >> (32 - (r))); v1 ^= v0; }
  TFR(13) TFR(15) TFR(26) TFR(6)   v0 += k1; v1 += k2 + 1u;
  TFR(17) TFR(29) TFR(16) TFR(24)  v0 += k2; v1 += k0 + 2u;
  TFR(13) TFR(15) TFR(26) TFR(6)   v0 += k0; v1 += k1 + 3u;
  TFR(17) TFR(29) TFR(16) TFR(24)  v0 += k1; v1 += k2 + 4u;
  TFR(13) TFR(15) TFR(26) TFR(6)   v0 += k2; v1 += k0 + 5u;
#undef TFR
  o0 = v0; o1 = v1;
}

__device__ __forceinline__ float jax_noise(unsigned k0, unsigned k1, unsigned idx) {
  unsigned o0, o1;
  tf2x32(k0, k1, 0u, idx, o0, o1);
  unsigned bits = o0 ^ o1;
  float u = __uint_as_float((bits >> 9) | 0x3f800000u) - 1.0f;
  const float lo = -0.99999994f;
  float val = u * 1.99999994f + lo;
  val = fmaxf(lo, val);
  return 0.1f * (1.4142135381698608f * erfinvf(val));
}

// ============ smem: A 128x96 bf16 stride 136; B 96x96 bf16 stride 136 ============
// stride 136 bf16 = 68 words; 68 mod 32 = 4 -> every ldmatrix phase hits 32 banks.
#define SASTRIDE 136
#define A_ELEMS (128 * SASTRIDE)
#define B_ELEMS (96 * SASTRIDE)
#define SMEM_BYTES ((A_ELEMS + B_ELEMS) * 2)

#define GEMM_PROLOG \
  extern __shared__ __align__(16) char smraw[]; \
  __nv_bfloat16* sm_a = reinterpret_cast<__nv_bfloat16*>(smraw); \
  __nv_bfloat16* sm_b = sm_a + A_ELEMS; \
  int tid = threadIdx.x; \
  int warp = tid >> 5, lane = tid & 31; \
  int wr = warp / 3, wc = warp % 3; \
  int gid = lane >> 2, tig = lane & 3; \
  int lrow = lane & 15, lsel = lane >> 4; \
  int row0 = blockIdx.x * 128; \
  unsigned aB0 = s2u(&sm_a[(wr * 32 + lrow) * SASTRIDE + lsel * 8]); \
  unsigned aB1 = aB0 + 16 * SASTRIDE * 2; \
  unsigned bB0 = s2u(&sm_b[lrow * SASTRIDE + wc * 32 + lsel * 8]); \
  unsigned bB1 = bB0 + 16 * 2;

// A fill: copy bf16 rows (LDK bf16 per row) starting at K0 into sm_a
#define LOAD_A_BF16(SRC, LDK, K0) \
  _Pragma("unroll") \
  for (int i = 0; i < 4; i++) { \
    int idx = tid + i * 384; int r = idx / 12, q = idx % 12; \
    *reinterpret_cast<uint4*>(&sm_a[r * SASTRIDE + q * 8]) = \
        *reinterpret_cast<const uint4*>(&(SRC)[(size_t)(row0 + r) * (LDK) + (K0) + q * 8]); \
  }

// LN from fp32 global SRC (row stride 96) -> bf16 into sm_a. One warp per row.
#define LN_TO_SMEM(SRC, G, Bv) \
  { \
    float g0 = (G)[lane], g1 = (G)[lane + 32], g2 = (G)[lane + 64]; \
    float b0 = (Bv)[lane], b1 = (Bv)[lane + 32], b2 = (Bv)[lane + 64]; \
    for (int r = warp; r < 128; r += 12) { \
      const float* xr = (SRC) + (size_t)(row0 + r) * 96; \
      float v0 = xr[lane], v1 = xr[lane + 32], v2 = xr[lane + 64]; \
      float s = v0 + v1 + v2, sq = v0 * v0 + v1 * v1 + v2 * v2; \
      _Pragma("unroll") \
      for (int o = 16; o; o >>= 1) { \
        s  += __shfl_xor_sync(0xffffffffu, s, o); \
        sq += __shfl_xor_sync(0xffffffffu, sq, o); \
      } \
      float mu = s * (1.0f / 96.0f); \
      float rs = rsqrtf(sq * (1.0f / 96.0f) - mu * mu + 1e-5f); \
      sm_a[r * SASTRIDE + lane]      = __float2bfloat16_rn((v0 - mu) * rs * g0 + b0); \
      sm_a[r * SASTRIDE + lane + 32] = __float2bfloat16_rn((v1 - mu) * rs * g1 + b1); \
      sm_a[r * SASTRIDE + lane + 64] = __float2bfloat16_rn((v2 - mu) * rs * g2 + b2); \
    } \
  }

// MMA over K=96 (6 k16 chunks), accumulate into acc[2][4][4]
#define MMA_K96_BF16 \
  _Pragma("unroll") \
  for (int kc = 0; kc < 6; kc++) { \
    unsigned a[2][4], bt[2][4]; \
    ldsm4 (a[0],  aB0 + kc * 32); \
    ldsm4 (a[1],  aB1 + kc * 32); \
    ldsm4t(bt[0], bB0 + kc * (16 * SASTRIDE * 2)); \
    ldsm4t(bt[1], bB1 + kc * (16 * SASTRIDE * 2)); \
    _Pragma("unroll") \
    for (int mt = 0; mt < 2; mt++) \
      _Pragma("unroll") \
      for (int nt = 0; nt < 4; nt++) \
        mma_bf16(acc[mt][nt], a[mt], bt[nt >> 1][(nt & 1) * 2], bt[nt >> 1][(nt & 1) * 2 + 1]); \
  }

// ---- fused LN1 + QKV ----
__global__ void __launch_bounds__(384, 2) qkv_kernel(const float* __restrict__ x,
                                                     const float* __restrict__ ln1g,
                                                     const float* __restrict__ ln1b,
                                                     const float* __restrict__ Wq,
                                                     const float* __restrict__ Wk,
                                                     const float* __restrict__ Wv) {
  GEMM_PROLOG
  LN_TO_SMEM(x, ln1g, ln1b)
  for (int w = 0; w < 3; w++) {
    const float* W   = (w == 0) ? Wq : (w == 1) ? Wk : Wv;
    float*       Out = (w == 0) ? g_q : (w == 1) ? g_k : g_v;
    __syncthreads();
#pragma unroll
    for (int i = 0; i < 6; i++) {                 // B: 96x96 from W[h,d,e]
      int idx = tid + i * 384; int r = idx / 24, c4 = idx % 24;
      int h = c4 >> 2, e4 = c4 & 3;
      float4 v = *reinterpret_cast<const float4*>(&W[h * 1536 + r * 16 + e4 * 4]);
      *reinterpret_cast<uint2*>(&sm_b[r * SASTRIDE + c4 * 4]) =
          make_uint2(pack_bf2(v.x, v.y), pack_bf2(v.z, v.w));
    }
    __syncthreads();
    float acc[2][4][4] = {};
    MMA_K96_BF16
#pragma unroll
    for (int mt = 0; mt < 2; mt++)
#pragma unroll
      for (int nt = 0; nt < 4; nt++) {
        int r0 = row0 + wr * 32 + mt * 16 + gid;
        int c0 = wc * 32 + nt * 8 + 2 * tig;
        int h = c0 >> 4, e = c0 & 15;
#pragma unroll
        for (int rr = 0; rr < 2; rr++) {
          int tok = r0 + rr * 8;
          int b_ = tok >> 8, t_ = tok & 255;
          *reinterpret_cast<float2*>(&Out[((b_ * 6 + h) * 256 + t_) * 16 + e]) =
              make_float2(acc[mt][nt][2 * rr], acc[mt][nt][2 * rr + 1]);
        }
      }
  }
}

// ---- attention: no-max softmax; output bf16 into g_h ----
__global__ void __launch_bounds__(256) attn_kernel() {
  int bh = blockIdx.x;
  __shared__ __align__(16) float ks[256][16];
  __shared__ __align__(16) float vs[256][16];
  const float* kb = g_k + bh * (256 * 16);
  const float* vb = g_v + bh * (256 * 16);
  for (int i = threadIdx.x; i < 1024; i += 256) {
    reinterpret_cast<float4*>(&ks[0][0])[i] = reinterpret_cast<const float4*>(kb)[i];
    reinterpret_cast<float4*>(&vs[0][0])[i] = reinterpret_cast<const float4*>(vb)[i];
  }
  __syncthreads();
  int t = threadIdx.x;
  const unsigned long long* qr =
      reinterpret_cast<const unsigned long long*>(g_q + (bh * 256 + t) * 16);
  unsigned long long q[8];
#pragma unroll
  for (int i = 0; i < 8; i++) q[i] = qr[i];
  float l = 0.0f;
  unsigned long long acc[8] = {};
  for (int s = 0; s <= t; s++) {
    const unsigned long long* kr = reinterpret_cast<const unsigned long long*>(ks[s]);
    unsigned long long d0 = mul2(q[0], kr[0]);
    unsigned long long d1 = mul2(q[1], kr[1]);
#pragma unroll
    for (int i = 2; i < 8; i += 2) {
      d0 = fma2(q[i],     kr[i],     d0);
      d1 = fma2(q[i + 1], kr[i + 1], d1);
    }
    float a0, a1, b0, b1;
    unpack2(d0, a0, a1); unpack2(d1, b0, b1);
    float p = __expf(((a0 + a1) + (b0 + b1)) * 0.25f);
    l += p;
    unsigned long long pd = f2x2(p, p);
    const unsigned long long* vr = reinterpret_cast<const unsigned long long*>(vs[s]);
#pragma unroll
    for (int i = 0; i < 8; i++) acc[i] = fma2(pd, vr[i], acc[i]);
  }
  float inv = 1.0f / l;
  int b_ = bh / 6, h_ = bh % 6;
  __nv_bfloat16* orow = g_h + ((size_t)(b_ * 256 + t)) * 96 + h_ * 16;
#pragma unroll
  for (int i = 0; i < 8; i++) {
    float lo, hi; unpack2(acc[i], lo, hi);
    *reinterpret_cast<__nv_bfloat162*>(&orow[2 * i]) =
        __float22bfloat162_rn(make_float2(lo * inv, hi * inv));
  }
}

// ---- projection + residual + noise1 ----
__global__ void __launch_bounds__(384, 2) proj_kernel(const float* __restrict__ Wp,
                                                      const float* __restrict__ bp,
                                                      const float* __restrict__ x,
                                                      unsigned nk0, unsigned nk1v) {
  GEMM_PROLOG
  LOAD_A_BF16(g_h, 96, 0)
#pragma unroll
  for (int i = 0; i < 6; i++) {
    int idx = tid + i * 384; int r = idx / 24, c4 = idx % 24;
    float4 v = *reinterpret_cast<const float4*>(&Wp[r * 96 + c4 * 4]);
    *reinterpret_cast<uint2*>(&sm_b[r * SASTRIDE + c4 * 4]) =
        make_uint2(pack_bf2(v.x, v.y), pack_bf2(v.z, v.w));
  }
  __syncthreads();
  float acc[2][4][4] = {};
  MMA_K96_BF16
#pragma unroll
  for (int mt = 0; mt < 2; mt++)
#pragma unroll
    for (int nt = 0; nt < 4; nt++) {
      int r0 = row0 + wr * 32 + mt * 16 + gid;
      int c0 = wc * 32 + nt * 8 + 2 * tig;
      float bp0 = bp[c0], bp1 = bp[c0 + 1];
#pragma unroll
      for (int rr = 0; rr < 2; rr++) {
        int i0 = (r0 + rr * 8) * 96 + c0;
        float o0 = x[i0]     + acc[mt][nt][2 * rr]     + bp0 + jax_noise(nk0, nk1v, (unsigned)i0);
        float o1 = x[i0 + 1] + acc[mt][nt][2 * rr + 1] + bp1 + jax_noise(nk0, nk1v, (unsigned)(i0 + 1));
        *reinterpret_cast<float2*>(&g_x1[i0]) = make_float2(o0, o1);
      }
    }
}

// ---- fused LN2 + FF1 (4 col groups); output bf16 g_f ----
__global__ void __launch_bounds__(384, 2) ff1_kernel(const float* __restrict__ W1,
                                                     const float* __restrict__ b1,
                                                     const float* __restrict__ ln2g,
                                                     const float* __restrict__ ln2b) {
  GEMM_PROLOG
  LN_TO_SMEM(g_x1, ln2g, ln2b)
  for (int grp = 0; grp < 4; grp++) {
    int co = grp * 96;
    __syncthreads();
#pragma unroll
    for (int i = 0; i < 6; i++) {
      int idx = tid + i * 384; int r = idx / 24, c4 = idx % 24;
      float4 v = *reinterpret_cast<const float4*>(&W1[r * 384 + co + c4 * 4]);
      *reinterpret_cast<uint2*>(&sm_b[r * SASTRIDE + c4 * 4]) =
          make_uint2(pack_bf2(v.x, v.y), pack_bf2(v.z, v.w));
    }
    __syncthreads();
    float acc[2][4][4] = {};
    MMA_K96_BF16
#pragma unroll
    for (int mt = 0; mt < 2; mt++)
#pragma unroll
      for (int nt = 0; nt < 4; nt++) {
        int r0 = row0 + wr * 32 + mt * 16 + gid;
        int c0 = wc * 32 + nt * 8 + 2 * tig;
        float bb0 = b1[co + c0], bb1 = b1[co + c0 + 1];
#pragma unroll
        for (int rr = 0; rr < 2; rr++) {
          int tok = r0 + rr * 8;
          *reinterpret_cast<__nv_bfloat162*>(&g_f[(size_t)tok * 384 + co + c0]) =
              __float22bfloat162_rn(make_float2(fmaxf(acc[mt][nt][2 * rr] + bb0, 0.0f),
                                                fmaxf(acc[mt][nt][2 * rr + 1] + bb1, 0.0f)));
        }
      }
  }
}

// ---- FF2 + residual + noise2 -> out (K=384 in 4 chunks) ----
__global__ void __launch_bounds__(384, 2) ff2_kernel(const float* __restrict__ W2,
                                                     const float* __restrict__ b2,
                                                     float* __restrict__ out,
                                                     unsigned nk0, unsigned nk1v) {
  GEMM_PROLOG
  float acc[2][4][4] = {};
  for (int kc4 = 0; kc4 < 4; kc4++) {
    int k0 = kc4 * 96;
    __syncthreads();
    LOAD_A_BF16(g_f, 384, k0)
#pragma unroll
    for (int i = 0; i < 6; i++) {
      int idx = tid + i * 384; int r = idx / 24, c4 = idx % 24;
      float4 v = *reinterpret_cast<const float4*>(&W2[(k0 + r) * 96 + c4 * 4]);
      *reinterpret_cast<uint2*>(&sm_b[r * SASTRIDE + c4 * 4]) =
          make_uint2(pack_bf2(v.x, v.y), pack_bf2(v.z, v.w));
    }
    __syncthreads();
    MMA_K96_BF16
  }
#pragma unroll
  for (int mt = 0; mt < 2; mt++)
#pragma unroll
    for (int nt = 0; nt < 4; nt++) {
      int r0 = row0 + wr * 32 + mt * 16 + gid;
      int c0 = wc * 32 + nt * 8 + 2 * tig;
      float bb0 = b2[c0], bb1 = b2[c0 + 1];
#pragma unroll
      for (int rr = 0; rr < 2; rr++) {
        int i0 = (r0 + rr * 8) * 96 + c0;
        float o0 = g_x1[i0]     + acc[mt][nt][2 * rr]     + bb0 + jax_noise(nk0, nk1v, (unsigned)i0);
        float o1 = g_x1[i0 + 1] + acc[mt][nt][2 * rr + 1] + bb1 + jax_noise(nk0, nk1v, (unsigned)(i0 + 1));
        *reinterpret_cast<float2*>(&out[i0]) = make_float2(o0, o1);
      }
    }
}

extern "C" void kernel_launch(void* const* d_in, const int* in_sizes, int n_in,
                              void* d_out, int out_size) {
  (void)in_sizes; (void)n_in; (void)out_size;
  const float* x    = (const float*)d_in[0];
  const float* Wq   = (const float*)d_in[1];
  const float* Wk   = (const float*)d_in[2];
  const float* Wv   = (const float*)d_in[3];
  const float* Wp   = (const float*)d_in[4];
  const float* bp   = (const float*)d_in[5];
  const float* ln1g = (const float*)d_in[6];
  const float* ln1b = (const float*)d_in[7];
  const float* ln2g = (const float*)d_in[8];
  const float* ln2b = (const float*)d_in[9];
  const float* W1   = (const float*)d_in[10];
  const float* b1   = (const float*)d_in[11];
  const float* W2   = (const float*)d_in[12];
  const float* b2   = (const float*)d_in[13];
  float* out = (float*)d_out;

  unsigned nk1_0, nk1_1, nk2_0, nk2_1;
  tf2x32(0u, 42u, 0u, 0u, nk1_0, nk1_1);
  tf2x32(0u, 42u, 0u, 1u, nk2_0, nk2_1);

  cudaFuncSetAttribute(qkv_kernel,  cudaFuncAttributeMaxDynamicSharedMemorySize, SMEM_BYTES);
  cudaFuncSetAttribute(proj_kernel, cudaFuncAttributeMaxDynamicSharedMemorySize, SMEM_BYTES);
  cudaFuncSetAttribute(ff1_kernel,  cudaFuncAttributeMaxDynamicSharedMemorySize, SMEM_BYTES);
  cudaFuncSetAttribute(ff2_kernel,  cudaFuncAttributeMaxDynamicSharedMemorySize, SMEM_BYTES);

  qkv_kernel <<<512, 384, SMEM_BYTES>>>(x, ln1g, ln1b, Wq, Wk, Wv);
  attn_kernel<<<1536, 256>>>();
  proj_kernel<<<512, 384, SMEM_BYTES>>>(Wp, bp, x, nk1_0, nk1_1);
  ff1_kernel <<<512, 384, SMEM_BYTES>>>(W1, b1, ln2g, ln2b);
  ff2_kernel <<<512, 384, SMEM_BYTES>>>(W2, b2, out, nk2_0, nk2_1);
}

// round 6
// speedup vs baseline: 2.4072x; 1.0349x over previous
#include <cuda_runtime.h>
#include <cuda_bf16.h>
#include <cstdint>

// Problem dims: B=256, T=256, D=96, H=6, E=16, DFF=384
#define NTOK 65536              // B*T

// ---------------- scratch (device globals; no allocations) ----------------
__device__ __nv_bfloat16 g_h [NTOK * 96];    // attn concat output (bf16)
__device__ float         g_q [NTOK * 96];    // [B*H, T, E] fp32
__device__ float         g_k [NTOK * 96];
__device__ float         g_v [NTOK * 96];
__device__ float         g_x1[NTOK * 96];    // residual after attention branch
__device__ __nv_bfloat16 g_f [NTOK * 384];   // FF hidden (bf16)

// pre-converted bf16 weights (k-major [k][n] layouts)
__device__ __nv_bfloat16 g_wq[96 * 96];
__device__ __nv_bfloat16 g_wk[96 * 96];
__device__ __nv_bfloat16 g_wv[96 * 96];
__device__ __nv_bfloat16 g_wp[96 * 96];
__device__ __nv_bfloat16 g_w1c[96 * 384];
__device__ __nv_bfloat16 g_w2c[384 * 96];

// ---------------- packed f32x2 helpers (attention) ----------------
__device__ __forceinline__ unsigned long long f2x2(float lo, float hi) {
  unsigned long long r; asm("mov.b64 %0, {%1, %2};" : "=l"(r) : "f"(lo), "f"(hi)); return r;
}
__device__ __forceinline__ unsigned long long fma2(unsigned long long a, unsigned long long b, unsigned long long c) {
  unsigned long long d; asm("fma.rn.f32x2 %0, %1, %2, %3;" : "=l"(d) : "l"(a), "l"(b), "l"(c)); return d;
}
__device__ __forceinline__ unsigned long long mul2(unsigned long long a, unsigned long long b) {
  unsigned long long d; asm("mul.rn.f32x2 %0, %1, %2;" : "=l"(d) : "l"(a), "l"(b)); return d;
}
__device__ __forceinline__ void unpack2(unsigned long long v, float &lo, float &hi) {
  asm("mov.b64 {%0, %1}, %2;" : "=f"(lo), "=f"(hi) : "l"(v));
}

// ---------------- bf16 mma + ldmatrix + cp.async helpers ----------------
__device__ __forceinline__ void ldsm4(unsigned (&r)[4], unsigned addr) {
  asm volatile("ldmatrix.sync.aligned.m8n8.x4.shared.b16 {%0,%1,%2,%3}, [%4];"
               : "=r"(r[0]), "=r"(r[1]), "=r"(r[2]), "=r"(r[3]) : "r"(addr));
}
__device__ __forceinline__ void ldsm4t(unsigned (&r)[4], unsigned addr) {
  asm volatile("ldmatrix.sync.aligned.m8n8.x4.trans.shared.b16 {%0,%1,%2,%3}, [%4];"
               : "=r"(r[0]), "=r"(r[1]), "=r"(r[2]), "=r"(r[3]) : "r"(addr));
}
__device__ __forceinline__ void mma_bf16(float (&d)[4], const unsigned (&a)[4], unsigned b0, unsigned b1) {
  asm volatile("mma.sync.aligned.m16n8k16.row.col.f32.bf16.bf16.f32 "
               "{%0,%1,%2,%3}, {%4,%5,%6,%7}, {%8,%9}, {%0,%1,%2,%3};"
               : "+f"(d[0]), "+f"(d[1]), "+f"(d[2]), "+f"(d[3])
               : "r"(a[0]), "r"(a[1]), "r"(a[2]), "r"(a[3]), "r"(b0), "r"(b1));
}
__device__ __forceinline__ unsigned s2u(const void* p) {
  return (unsigned)__cvta_generic_to_shared(p);
}
__device__ __forceinline__ void cp16(unsigned dst, const void* src) {
  asm volatile("cp.async.cg.shared.global [%0], [%1], 16;" :: "r"(dst), "l"(src));
}
#define CP_COMMIT asm volatile("cp.async.commit_group;")
#define CP_WAIT(N) asm volatile("cp.async.wait_group %0;" :: "n"(N))

// ---------------- JAX threefry-2x32 (20 rounds) ----------------
__host__ __device__ __forceinline__ void tf2x32(unsigned k0, unsigned k1,
                                                unsigned x0, unsigned x1,
                                                unsigned &o0, unsigned &o1) {
  unsigned k2 = k0 ^ k1 ^ 0x1BD11BDAu;
  unsigned v0 = x0 + k0, v1 = x1 + k1;
#define TFR(r) { v0 += v1; v1 = (v1 << (r)) | (v1 >> (32 - (r))); v1 ^= v0; }
  TFR(13) TFR(15) TFR(26) TFR(6)   v0 += k1; v1 += k2 + 1u;
  TFR(17) TFR(29) TFR(16) TFR(24)  v0 += k2; v1 += k0 + 2u;
  TFR(13) TFR(15) TFR(26) TFR(6)   v0 += k0; v1 += k1 + 3u;
  TFR(17) TFR(29) TFR(16) TFR(24)  v0 += k1; v1 += k2 + 4u;
  TFR(13) TFR(15) TFR(26) TFR(6)   v0 += k2; v1 += k0 + 5u;
#undef TFR
  o0 = v0; o1 = v1;
}

__device__ __forceinline__ float jax_noise(unsigned k0, unsigned k1, unsigned idx) {
  unsigned o0, o1;
  tf2x32(k0, k1, 0u, idx, o0, o1);
  unsigned bits = o0 ^ o1;
  float u = __uint_as_float((bits >> 9) | 0x3f800000u) - 1.0f;
  const float lo = -0.99999994f;
  float val = u * 1.99999994f + lo;
  val = fmaxf(lo, val);
  return 0.1f * (1.4142135381698608f * erfinvf(val));
}

// ---------------- weight prep: fp32 -> bf16, gather into [k][n] ----------------
__global__ void __launch_bounds__(256) prep_kernel(const float* __restrict__ Wq,
                                                   const float* __restrict__ Wk,
                                                   const float* __restrict__ Wv,
                                                   const float* __restrict__ Wp,
                                                   const float* __restrict__ W1,
                                                   const float* __restrict__ W2) {
  int i = blockIdx.x * 256 + threadIdx.x;
  if (i < 9216) {
    int r = i / 96, c = i % 96;
    int h = c >> 4, e = c & 15;
    int s = h * 1536 + r * 16 + e;
    g_wq[i] = __float2bfloat16_rn(Wq[s]);
    g_wk[i] = __float2bfloat16_rn(Wk[s]);
    g_wv[i] = __float2bfloat16_rn(Wv[s]);
    g_wp[i] = __float2bfloat16_rn(Wp[i]);
  } else if (i < 9216 + 36864) {
    int j = i - 9216;
    g_w1c[j] = __float2bfloat16_rn(W1[j]);
  } else if (i < 9216 + 2 * 36864) {
    int j = i - 9216 - 36864;
    g_w2c[j] = __float2bfloat16_rn(W2[j]);
  }
}

// ============ smem: A 128x96 bf16 stride 136; B double-buffered 96x96 ============
#define SASTRIDE 136
#define A_ELEMS (128 * SASTRIDE)
#define B_ELEMS (96 * SASTRIDE)
#define SMEM_BYTES ((A_ELEMS + 2 * B_ELEMS) * 2)

#define GEMM_PROLOG \
  extern __shared__ __align__(16) char smraw[]; \
  __nv_bfloat16* sm_a  = reinterpret_cast<__nv_bfloat16*>(smraw); \
  __nv_bfloat16* sm_b0 = sm_a + A_ELEMS; \
  __nv_bfloat16* sm_b1 = sm_b0 + B_ELEMS; \
  int tid = threadIdx.x; \
  int warp = tid >> 5, lane = tid & 31; \
  int wr = warp / 3, wc = warp % 3; \
  int gid = lane >> 2, tig = lane & 3; \
  int lrow = lane & 15, lsel = lane >> 4; \
  int row0 = blockIdx.x * 128; \
  unsigned aB0 = s2u(&sm_a[(wr * 32 + lrow) * SASTRIDE + lsel * 8]); \
  unsigned aB1 = aB0 + 16 * SASTRIDE * 2;

// cp.async B tile: 96 rows x 96 bf16, SRC row stride LD bf16, col offset OFF
#define CPA_B(BUF, SRC, LD, OFF) \
  _Pragma("unroll") \
  for (int i = 0; i < 3; i++) { \
    int c = tid + i * 384; int r = c / 12, q = c % 12; \
    cp16(s2u(&(BUF)[r * SASTRIDE + q * 8]), (SRC) + r * (LD) + (OFF) + q * 8); \
  }

// cp.async A tile: 128 rows x 96 bf16 from bf16 global, row stride LD, col off OFF
#define CPA_A(SRC, LD, OFF) \
  _Pragma("unroll") \
  for (int i = 0; i < 4; i++) { \
    int c = tid + i * 384; int r = c / 12, q = c % 12; \
    cp16(s2u(&sm_a[r * SASTRIDE + q * 8]), (SRC) + (size_t)(row0 + r) * (LD) + (OFF) + q * 8); \
  }

// LN from fp32 global SRC (row stride 96) -> bf16 into sm_a. One warp per row.
#define LN_TO_SMEM(SRC, G, Bv) \
  { \
    float g0 = (G)[lane], g1 = (G)[lane + 32], g2 = (G)[lane + 64]; \
    float b0 = (Bv)[lane], b1 = (Bv)[lane + 32], b2 = (Bv)[lane + 64]; \
    for (int r = warp; r < 128; r += 12) { \
      const float* xr = (SRC) + (size_t)(row0 + r) * 96; \
      float v0 = xr[lane], v1 = xr[lane + 32], v2 = xr[lane + 64]; \
      float s = v0 + v1 + v2, sq = v0 * v0 + v1 * v1 + v2 * v2; \
      _Pragma("unroll") \
      for (int o = 16; o; o >>= 1) { \
        s  += __shfl_xor_sync(0xffffffffu, s, o); \
        sq += __shfl_xor_sync(0xffffffffu, sq, o); \
      } \
      float mu = s * (1.0f / 96.0f); \
      float rs = rsqrtf(sq * (1.0f / 96.0f) - mu * mu + 1e-5f); \
      sm_a[r * SASTRIDE + lane]      = __float2bfloat16_rn((v0 - mu) * rs * g0 + b0); \
      sm_a[r * SASTRIDE + lane + 32] = __float2bfloat16_rn((v1 - mu) * rs * g1 + b1); \
      sm_a[r * SASTRIDE + lane + 64] = __float2bfloat16_rn((v2 - mu) * rs * g2 + b2); \
    } \
  }

// MMA over K=96 (6 k16 chunks) against B buffer BB, accumulate into acc[2][4][4]
#define MMA_K96_BF16(BB) \
  { \
    unsigned bb0 = s2u(&(BB)[lrow * SASTRIDE + wc * 32 + lsel * 8]); \
    unsigned bb1 = bb0 + 16 * 2; \
    _Pragma("unroll") \
    for (int kc = 0; kc < 6; kc++) { \
      unsigned a[2][4], bt[2][4]; \
      ldsm4 (a[0],  aB0 + kc * 32); \
      ldsm4 (a[1],  aB1 + kc * 32); \
      ldsm4t(bt[0], bb0 + kc * (16 * SASTRIDE * 2)); \
      ldsm4t(bt[1], bb1 + kc * (16 * SASTRIDE * 2)); \
      _Pragma("unroll") \
      for (int mt = 0; mt < 2; mt++) \
        _Pragma("unroll") \
        for (int nt = 0; nt < 4; nt++) \
          mma_bf16(acc[mt][nt], a[mt], bt[nt >> 1][(nt & 1) * 2], bt[nt >> 1][(nt & 1) * 2 + 1]); \
    } \
  }

// ---- fused LN1 + QKV: B tiles double-buffered via cp.async ----
__global__ void __launch_bounds__(384, 2) qkv_kernel(const float* __restrict__ x,
                                                     const float* __restrict__ ln1g,
                                                     const float* __restrict__ ln1b) {
  GEMM_PROLOG
  CPA_B(sm_b0, g_wq, 96, 0)
  CP_COMMIT;
  LN_TO_SMEM(x, ln1g, ln1b)
  for (int w = 0; w < 3; w++) {
    CP_WAIT(0);
    __syncthreads();
    if (w == 0) { CPA_B(sm_b1, g_wk, 96, 0) CP_COMMIT; }
    if (w == 1) { CPA_B(sm_b0, g_wv, 96, 0) CP_COMMIT; }
    float acc[2][4][4] = {};
    if (w & 1) { MMA_K96_BF16(sm_b1) } else { MMA_K96_BF16(sm_b0) }
    float* Out = (w == 0) ? g_q : (w == 1) ? g_k : g_v;
#pragma unroll
    for (int mt = 0; mt < 2; mt++)
#pragma unroll
      for (int nt = 0; nt < 4; nt++) {
        int r0 = row0 + wr * 32 + mt * 16 + gid;
        int c0 = wc * 32 + nt * 8 + 2 * tig;
        int h = c0 >> 4, e = c0 & 15;
#pragma unroll
        for (int rr = 0; rr < 2; rr++) {
          int tok = r0 + rr * 8;
          int b_ = tok >> 8, t_ = tok & 255;
          *reinterpret_cast<float2*>(&Out[((b_ * 6 + h) * 256 + t_) * 16 + e]) =
              make_float2(acc[mt][nt][2 * rr], acc[mt][nt][2 * rr + 1]);
        }
      }
  }
}

// ---- attention: no-max softmax; output bf16 into g_h ----
__global__ void __launch_bounds__(256) attn_kernel() {
  int bh = blockIdx.x;
  __shared__ __align__(16) float ks[256][16];
  __shared__ __align__(16) float vs[256][16];
  const float* kb = g_k + bh * (256 * 16);
  const float* vb = g_v + bh * (256 * 16);
  for (int i = threadIdx.x; i < 1024; i += 256) {
    reinterpret_cast<float4*>(&ks[0][0])[i] = reinterpret_cast<const float4*>(kb)[i];
    reinterpret_cast<float4*>(&vs[0][0])[i] = reinterpret_cast<const float4*>(vb)[i];
  }
  __syncthreads();
  int t = threadIdx.x;
  const unsigned long long* qr =
      reinterpret_cast<const unsigned long long*>(g_q + (bh * 256 + t) * 16);
  unsigned long long q[8];
#pragma unroll
  for (int i = 0; i < 8; i++) q[i] = qr[i];
  float l = 0.0f;
  unsigned long long acc[8] = {};
  for (int s = 0; s <= t; s++) {
    const unsigned long long* kr = reinterpret_cast<const unsigned long long*>(ks[s]);
    unsigned long long d0 = mul2(q[0], kr[0]);
    unsigned long long d1 = mul2(q[1], kr[1]);
#pragma unroll
    for (int i = 2; i < 8; i += 2) {
      d0 = fma2(q[i],     kr[i],     d0);
      d1 = fma2(q[i + 1], kr[i + 1], d1);
    }
    float a0, a1, b0, b1;
    unpack2(d0, a0, a1); unpack2(d1, b0, b1);
    float p = __expf(((a0 + a1) + (b0 + b1)) * 0.25f);
    l += p;
    unsigned long long pd = f2x2(p, p);
    const unsigned long long* vr = reinterpret_cast<const unsigned long long*>(vs[s]);
#pragma unroll
    for (int i = 0; i < 8; i++) acc[i] = fma2(pd, vr[i], acc[i]);
  }
  float inv = 1.0f / l;
  int b_ = bh / 6, h_ = bh % 6;
  __nv_bfloat16* orow = g_h + ((size_t)(b_ * 256 + t)) * 96 + h_ * 16;
#pragma unroll
  for (int i = 0; i < 8; i++) {
    float lo, hi; unpack2(acc[i], lo, hi);
    *reinterpret_cast<__nv_bfloat162*>(&orow[2 * i]) =
        __float22bfloat162_rn(make_float2(lo * inv, hi * inv));
  }
}

// ---- projection + residual + noise1 (A and B both cp.async) ----
__global__ void __launch_bounds__(384, 2) proj_kernel(const float* __restrict__ bp,
                                                      const float* __restrict__ x,
                                                      unsigned nk0, unsigned nk1v) {
  GEMM_PROLOG
  CPA_A(g_h, 96, 0)
  CPA_B(sm_b0, g_wp, 96, 0)
  CP_COMMIT;
  CP_WAIT(0);
  __syncthreads();
  float acc[2][4][4] = {};
  MMA_K96_BF16(sm_b0)
#pragma unroll
  for (int mt = 0; mt < 2; mt++)
#pragma unroll
    for (int nt = 0; nt < 4; nt++) {
      int r0 = row0 + wr * 32 + mt * 16 + gid;
      int c0 = wc * 32 + nt * 8 + 2 * tig;
      float bp0 = bp[c0], bp1 = bp[c0 + 1];
#pragma unroll
      for (int rr = 0; rr < 2; rr++) {
        int i0 = (r0 + rr * 8) * 96 + c0;
        float o0 = x[i0]     + acc[mt][nt][2 * rr]     + bp0 + jax_noise(nk0, nk1v, (unsigned)i0);
        float o1 = x[i0 + 1] + acc[mt][nt][2 * rr + 1] + bp1 + jax_noise(nk0, nk1v, (unsigned)(i0 + 1));
        *reinterpret_cast<float2*>(&g_x1[i0]) = make_float2(o0, o1);
      }
    }
}

// ---- fused LN2 + FF1 (4 col groups, B double-buffered) ----
__global__ void __launch_bounds__(384, 2) ff1_kernel(const float* __restrict__ b1,
                                                     const float* __restrict__ ln2g,
                                                     const float* __restrict__ ln2b) {
  GEMM_PROLOG
  CPA_B(sm_b0, g_w1c, 384, 0)
  CP_COMMIT;
  LN_TO_SMEM(g_x1, ln2g, ln2b)
  for (int grp = 0; grp < 4; grp++) {
    int co = grp * 96;
    CP_WAIT(0);
    __syncthreads();
    if (grp < 3) {
      if (grp & 1) { CPA_B(sm_b0, g_w1c, 384, co + 96) }
      else         { CPA_B(sm_b1, g_w1c, 384, co + 96) }
      CP_COMMIT;
    }
    float acc[2][4][4] = {};
    if (grp & 1) { MMA_K96_BF16(sm_b1) } else { MMA_K96_BF16(sm_b0) }
#pragma unroll
    for (int mt = 0; mt < 2; mt++)
#pragma unroll
      for (int nt = 0; nt < 4; nt++) {
        int r0 = row0 + wr * 32 + mt * 16 + gid;
        int c0 = wc * 32 + nt * 8 + 2 * tig;
        float bb0 = b1[co + c0], bb1 = b1[co + c0 + 1];
#pragma unroll
        for (int rr = 0; rr < 2; rr++) {
          int tok = r0 + rr * 8;
          *reinterpret_cast<__nv_bfloat162*>(&g_f[(size_t)tok * 384 + co + c0]) =
              __float22bfloat162_rn(make_float2(fmaxf(acc[mt][nt][2 * rr] + bb0, 0.0f),
                                                fmaxf(acc[mt][nt][2 * rr + 1] + bb1, 0.0f)));
        }
      }
  }
}

// ---- FF2 + residual + noise2 -> out (K=384 in 4 chunks; B pipelined) ----
__global__ void __launch_bounds__(384, 2) ff2_kernel(const float* __restrict__ b2,
                                                     float* __restrict__ out,
                                                     unsigned nk0, unsigned nk1v) {
  GEMM_PROLOG
  CPA_B(sm_b0, g_w2c, 96, 0)       // B(0): rows 0..95 of W2
  CP_COMMIT;
  float acc[2][4][4] = {};
#pragma unroll
  for (int g = 0; g < 4; g++) {
    __syncthreads();                        // prior MMA done before A overwrite
    CPA_A(g_f, 384, g * 96)
    CP_COMMIT;
    if (g < 3) {
      const __nv_bfloat16* src = g_w2c + (g + 1) * 9216;
      if (g & 1) { CPA_B(sm_b0, src, 96, 0) }
      else       { CPA_B(sm_b1, src, 96, 0) }
      CP_COMMIT;
    }
    if (g < 3) { CP_WAIT(1); } else { CP_WAIT(0); }
    __syncthreads();
    if (g & 1) { MMA_K96_BF16(sm_b1) } else { MMA_K96_BF16(sm_b0) }
  }
#pragma unroll
  for (int mt = 0; mt < 2; mt++)
#pragma unroll
    for (int nt = 0; nt < 4; nt++) {
      int r0 = row0 + wr * 32 + mt * 16 + gid;
      int c0 = wc * 32 + nt * 8 + 2 * tig;
      float bb0 = b2[c0], bb1 = b2[c0 + 1];
#pragma unroll
      for (int rr = 0; rr < 2; rr++) {
        int i0 = (r0 + rr * 8) * 96 + c0;
        float o0 = g_x1[i0]     + acc[mt][nt][2 * rr]     + bb0 + jax_noise(nk0, nk1v, (unsigned)i0);
        float o1 = g_x1[i0 + 1] + acc[mt][nt][2 * rr + 1] + bb1 + jax_noise(nk0, nk1v, (unsigned)(i0 + 1));
        *reinterpret_cast<float2*>(&out[i0]) = make_float2(o0, o1);
      }
    }
}

extern "C" void kernel_launch(void* const* d_in, const int* in_sizes, int n_in,
                              void* d_out, int out_size) {
  (void)in_sizes; (void)n_in; (void)out_size;
  const float* x    = (const float*)d_in[0];
  const float* Wq   = (const float*)d_in[1];
  const float* Wk   = (const float*)d_in[2];
  const float* Wv   = (const float*)d_in[3];
  const float* Wp   = (const float*)d_in[4];
  const float* bp   = (const float*)d_in[5];
  const float* ln1g = (const float*)d_in[6];
  const float* ln1b = (const float*)d_in[7];
  const float* ln2g = (const float*)d_in[8];
  const float* ln2b = (const float*)d_in[9];
  const float* W1   = (const float*)d_in[10];
  const float* b1   = (const float*)d_in[11];
  const float* W2   = (const float*)d_in[12];
  const float* b2   = (const float*)d_in[13];
  float* out = (float*)d_out;

  unsigned nk1_0, nk1_1, nk2_0, nk2_1;
  tf2x32(0u, 42u, 0u, 0u, nk1_0, nk1_1);
  tf2x32(0u, 42u, 0u, 1u, nk2_0, nk2_1);

  cudaFuncSetAttribute(qkv_kernel,  cudaFuncAttributeMaxDynamicSharedMemorySize, SMEM_BYTES);
  cudaFuncSetAttribute(proj_kernel, cudaFuncAttributeMaxDynamicSharedMemorySize, SMEM_BYTES);
  cudaFuncSetAttribute(ff1_kernel,  cudaFuncAttributeMaxDynamicSharedMemorySize, SMEM_BYTES);
  cudaFuncSetAttribute(ff2_kernel,  cudaFuncAttributeMaxDynamicSharedMemorySize, SMEM_BYTES);

  prep_kernel<<<324, 256>>>(Wq, Wk, Wv, Wp, W1, W2);
  qkv_kernel <<<512, 384, SMEM_BYTES>>>(x, ln1g, ln1b);
  attn_kernel<<<1536, 256>>>();
  proj_kernel<<<512, 384, SMEM_BYTES>>>(bp, x, nk1_0, nk1_1);
  ff1_kernel <<<512, 384, SMEM_BYTES>>>(b1, ln2g, ln2b);
  ff2_kernel <<<512, 384, SMEM_BYTES>>>(b2, out, nk2_0, nk2_1);
}

// round 7
// speedup vs baseline: 3.3301x; 1.3834x over previous
#include <cuda_runtime.h>
#include <cuda_bf16.h>
#include <cstdint>

// Problem dims: B=256, T=256, D=96, H=6, E=16, DFF=384
#define NTOK 65536              // B*T

// ---------------- scratch (device globals; no allocations) ----------------
__device__ __nv_bfloat16 g_h [NTOK * 96];    // attn concat output (bf16)
__device__ __nv_bfloat16 g_q [NTOK * 96];    // [B*H, T, E] bf16
__device__ __nv_bfloat16 g_k [NTOK * 96];
__device__ __nv_bfloat16 g_v [NTOK * 96];
__device__ float         g_x1[NTOK * 96];    // residual after attention branch
__device__ __nv_bfloat16 g_f [NTOK * 384];   // FF hidden (bf16)

// pre-converted bf16 weights (k-major [k][n] layouts)
__device__ __nv_bfloat16 g_wq[96 * 96];
__device__ __nv_bfloat16 g_wk[96 * 96];
__device__ __nv_bfloat16 g_wv[96 * 96];
__device__ __nv_bfloat16 g_wp[96 * 96];
__device__ __nv_bfloat16 g_w1c[96 * 384];
__device__ __nv_bfloat16 g_w2c[384 * 96];

// ---------------- bf16 mma + ldmatrix + cp.async helpers ----------------
__device__ __forceinline__ void ldsm4(unsigned (&r)[4], unsigned addr) {
  asm volatile("ldmatrix.sync.aligned.m8n8.x4.shared.b16 {%0,%1,%2,%3}, [%4];"
               : "=r"(r[0]), "=r"(r[1]), "=r"(r[2]), "=r"(r[3]) : "r"(addr));
}
__device__ __forceinline__ void ldsm4t(unsigned (&r)[4], unsigned addr) {
  asm volatile("ldmatrix.sync.aligned.m8n8.x4.trans.shared.b16 {%0,%1,%2,%3}, [%4];"
               : "=r"(r[0]), "=r"(r[1]), "=r"(r[2]), "=r"(r[3]) : "r"(addr));
}
__device__ __forceinline__ void mma_bf16(float (&d)[4], const unsigned (&a)[4], unsigned b0, unsigned b1) {
  asm volatile("mma.sync.aligned.m16n8k16.row.col.f32.bf16.bf16.f32 "
               "{%0,%1,%2,%3}, {%4,%5,%6,%7}, {%8,%9}, {%0,%1,%2,%3};"
               : "+f"(d[0]), "+f"(d[1]), "+f"(d[2]), "+f"(d[3])
               : "r"(a[0]), "r"(a[1]), "r"(a[2]), "r"(a[3]), "r"(b0), "r"(b1));
}
__device__ __forceinline__ unsigned s2u(const void* p) {
  return (unsigned)__cvta_generic_to_shared(p);
}
__device__ __forceinline__ void cp16(unsigned dst, const void* src) {
  asm volatile("cp.async.cg.shared.global [%0], [%1], 16;" :: "r"(dst), "l"(src));
}
#define CP_COMMIT asm volatile("cp.async.commit_group;")
#define CP_WAIT(N) asm volatile("cp.async.wait_group %0;" :: "n"(N))
__device__ __forceinline__ unsigned pack_bf2(float lo, float hi) {
  __nv_bfloat162 h = __float22bfloat162_rn(make_float2(lo, hi));
  return *reinterpret_cast<unsigned*>(&h);
}

// ---------------- JAX threefry-2x32 (20 rounds) ----------------
__host__ __device__ __forceinline__ void tf2x32(unsigned k0, unsigned k1,
                                                unsigned x0, unsigned x1,
                                                unsigned &o0, unsigned &o1) {
  unsigned k2 = k0 ^ k1 ^ 0x1BD11BDAu;
  unsigned v0 = x0 + k0, v1 = x1 + k1;
#define TFR(r) { v0 += v1; v1 = (v1 << (r)) | (v1 >> (32 - (r))); v1 ^= v0; }
  TFR(13) TFR(15) TFR(26) TFR(6)   v0 += k1; v1 += k2 + 1u;
  TFR(17) TFR(29) TFR(16) TFR(24)  v0 += k2; v1 += k0 + 2u;
  TFR(13) TFR(15) TFR(26) TFR(6)   v0 += k0; v1 += k1 + 3u;
  TFR(17) TFR(29) TFR(16) TFR(24)  v0 += k1; v1 += k2 + 4u;
  TFR(13) TFR(15) TFR(26) TFR(6)   v0 += k2; v1 += k0 + 5u;
#undef TFR
  o0 = v0; o1 = v1;
}

__device__ __forceinline__ float jax_noise(unsigned k0, unsigned k1, unsigned idx) {
  unsigned o0, o1;
  tf2x32(k0, k1, 0u, idx, o0, o1);
  unsigned bits = o0 ^ o1;
  float u = __uint_as_float((bits >> 9) | 0x3f800000u) - 1.0f;
  const float lo = -0.99999994f;
  float val = u * 1.99999994f + lo;
  val = fmaxf(lo, val);
  return 0.1f * (1.4142135381698608f * erfinvf(val));
}

// ---------------- weight prep: fp32 -> bf16, gather into [k][n] ----------------
__global__ void __launch_bounds__(256) prep_kernel(const float* __restrict__ Wq,
                                                   const float* __restrict__ Wk,
                                                   const float* __restrict__ Wv,
                                                   const float* __restrict__ Wp,
                                                   const float* __restrict__ W1,
                                                   const float* __restrict__ W2) {
  int i = blockIdx.x * 256 + threadIdx.x;
  if (i < 9216) {
    int r = i / 96, c = i % 96;
    int h = c >> 4, e = c & 15;
    int s = h * 1536 + r * 16 + e;
    g_wq[i] = __float2bfloat16_rn(Wq[s]);
    g_wk[i] = __float2bfloat16_rn(Wk[s]);
    g_wv[i] = __float2bfloat16_rn(Wv[s]);
    g_wp[i] = __float2bfloat16_rn(Wp[i]);
  } else if (i < 9216 + 36864) {
    int j = i - 9216;
    g_w1c[j] = __float2bfloat16_rn(W1[j]);
  } else if (i < 9216 + 2 * 36864) {
    int j = i - 9216 - 36864;
    g_w2c[j] = __float2bfloat16_rn(W2[j]);
  }
}

// ============ smem: A 128x96 bf16 stride 136; B double-buffered 96x96 ============
#define SASTRIDE 136
#define A_ELEMS (128 * SASTRIDE)
#define B_ELEMS (96 * SASTRIDE)
#define SMEM_BYTES ((A_ELEMS + 2 * B_ELEMS) * 2)

#define GEMM_PROLOG \
  extern __shared__ __align__(16) char smraw[]; \
  __nv_bfloat16* sm_a  = reinterpret_cast<__nv_bfloat16*>(smraw); \
  __nv_bfloat16* sm_b0 = sm_a + A_ELEMS; \
  __nv_bfloat16* sm_b1 = sm_b0 + B_ELEMS; \
  int tid = threadIdx.x; \
  int warp = tid >> 5, lane = tid & 31; \
  int wr = warp / 3, wc = warp % 3; \
  int gid = lane >> 2, tig = lane & 3; \
  int lrow = lane & 15, lsel = lane >> 4; \
  int row0 = blockIdx.x * 128; \
  unsigned aB0 = s2u(&sm_a[(wr * 32 + lrow) * SASTRIDE + lsel * 8]); \
  unsigned aB1 = aB0 + 16 * SASTRIDE * 2;

#define CPA_B(BUF, SRC, LD, OFF) \
  _Pragma("unroll") \
  for (int i = 0; i < 3; i++) { \
    int c = tid + i * 384; int r = c / 12, q = c % 12; \
    cp16(s2u(&(BUF)[r * SASTRIDE + q * 8]), (SRC) + r * (LD) + (OFF) + q * 8); \
  }

#define CPA_A(SRC, LD, OFF) \
  _Pragma("unroll") \
  for (int i = 0; i < 4; i++) { \
    int c = tid + i * 384; int r = c / 12, q = c % 12; \
    cp16(s2u(&sm_a[r * SASTRIDE + q * 8]), (SRC) + (size_t)(row0 + r) * (LD) + (OFF) + q * 8); \
  }

#define LN_TO_SMEM(SRC, G, Bv) \
  { \
    float g0 = (G)[lane], g1 = (G)[lane + 32], g2 = (G)[lane + 64]; \
    float b0 = (Bv)[lane], b1 = (Bv)[lane + 32], b2 = (Bv)[lane + 64]; \
    for (int r = warp; r < 128; r += 12) { \
      const float* xr = (SRC) + (size_t)(row0 + r) * 96; \
      float v0 = xr[lane], v1 = xr[lane + 32], v2 = xr[lane + 64]; \
      float s = v0 + v1 + v2, sq = v0 * v0 + v1 * v1 + v2 * v2; \
      _Pragma("unroll") \
      for (int o = 16; o; o >>= 1) { \
        s  += __shfl_xor_sync(0xffffffffu, s, o); \
        sq += __shfl_xor_sync(0xffffffffu, sq, o); \
      } \
      float mu = s * (1.0f / 96.0f); \
      float rs = rsqrtf(sq * (1.0f / 96.0f) - mu * mu + 1e-5f); \
      sm_a[r * SASTRIDE + lane]      = __float2bfloat16_rn((v0 - mu) * rs * g0 + b0); \
      sm_a[r * SASTRIDE + lane + 32] = __float2bfloat16_rn((v1 - mu) * rs * g1 + b1); \
      sm_a[r * SASTRIDE + lane + 64] = __float2bfloat16_rn((v2 - mu) * rs * g2 + b2); \
    } \
  }

#define MMA_K96_BF16(BB) \
  { \
    unsigned bb0 = s2u(&(BB)[lrow * SASTRIDE + wc * 32 + lsel * 8]); \
    unsigned bb1 = bb0 + 16 * 2; \
    _Pragma("unroll") \
    for (int kc = 0; kc < 6; kc++) { \
      unsigned a[2][4], bt[2][4]; \
      ldsm4 (a[0],  aB0 + kc * 32); \
      ldsm4 (a[1],  aB1 + kc * 32); \
      ldsm4t(bt[0], bb0 + kc * (16 * SASTRIDE * 2)); \
      ldsm4t(bt[1], bb1 + kc * (16 * SASTRIDE * 2)); \
      _Pragma("unroll") \
      for (int mt = 0; mt < 2; mt++) \
        _Pragma("unroll") \
        for (int nt = 0; nt < 4; nt++) \
          mma_bf16(acc[mt][nt], a[mt], bt[nt >> 1][(nt & 1) * 2], bt[nt >> 1][(nt & 1) * 2 + 1]); \
    } \
  }

// ---- fused LN1 + QKV: B tiles double-buffered; bf16 q/k/v out ----
__global__ void __launch_bounds__(384, 2) qkv_kernel(const float* __restrict__ x,
                                                     const float* __restrict__ ln1g,
                                                     const float* __restrict__ ln1b) {
  GEMM_PROLOG
  CPA_B(sm_b0, g_wq, 96, 0)
  CP_COMMIT;
  LN_TO_SMEM(x, ln1g, ln1b)
  for (int w = 0; w < 3; w++) {
    CP_WAIT(0);
    __syncthreads();
    if (w == 0) { CPA_B(sm_b1, g_wk, 96, 0) CP_COMMIT; }
    if (w == 1) { CPA_B(sm_b0, g_wv, 96, 0) CP_COMMIT; }
    float acc[2][4][4] = {};
    if (w & 1) { MMA_K96_BF16(sm_b1) } else { MMA_K96_BF16(sm_b0) }
    __nv_bfloat16* Out = (w == 0) ? g_q : (w == 1) ? g_k : g_v;
#pragma unroll
    for (int mt = 0; mt < 2; mt++)
#pragma unroll
      for (int nt = 0; nt < 4; nt++) {
        int r0 = row0 + wr * 32 + mt * 16 + gid;
        int c0 = wc * 32 + nt * 8 + 2 * tig;
        int h = c0 >> 4, e = c0 & 15;
#pragma unroll
        for (int rr = 0; rr < 2; rr++) {
          int tok = r0 + rr * 8;
          int b_ = tok >> 8, t_ = tok & 255;
          *reinterpret_cast<__nv_bfloat162*>(&Out[((b_ * 6 + h) * 256 + t_) * 16 + e]) =
              __float22bfloat162_rn(make_float2(acc[mt][nt][2 * rr], acc[mt][nt][2 * rr + 1]));
        }
      }
  }
}

// ---- tensor-core flash attention: block per (b,h), warp per 32 Q rows ----
// smem stride 24 bf16 (12 words/row, 12r mod 32 covers all banks -> conflict-free ldsm)
__global__ void __launch_bounds__(256) attn_kernel() {
  int bh = blockIdx.x;
  __shared__ __align__(16) __nv_bfloat16 qs[256 * 24];
  __shared__ __align__(16) __nv_bfloat16 ks[256 * 24];
  __shared__ __align__(16) __nv_bfloat16 vs[256 * 24];
  const __nv_bfloat16* qb = g_q + (size_t)bh * 4096;
  const __nv_bfloat16* kb = g_k + (size_t)bh * 4096;
  const __nv_bfloat16* vb = g_v + (size_t)bh * 4096;
  int tid = threadIdx.x;
#pragma unroll
  for (int i = 0; i < 2; i++) {
    int idx = tid + i * 256;
    int r = idx >> 1, half = idx & 1;
    cp16(s2u(&qs[r * 24 + half * 8]), qb + r * 16 + half * 8);
    cp16(s2u(&ks[r * 24 + half * 8]), kb + r * 16 + half * 8);
    cp16(s2u(&vs[r * 24 + half * 8]), vb + r * 16 + half * 8);
  }
  CP_COMMIT;
  CP_WAIT(0);
  __syncthreads();
  int warp = tid >> 5, lane = tid & 31;
  int gid = lane >> 2, tig = lane & 3;
  int lrow = lane & 15, lsel = lane >> 4;
  int r0 = warp * 32;

  unsigned qa[2][4];
  ldsm4(qa[0], s2u(&qs[(r0 + lrow) * 24 + lsel * 8]));
  ldsm4(qa[1], s2u(&qs[(r0 + 16 + lrow) * 24 + lsel * 8]));

  float o[2][2][4] = {};
  float lsum[2][2] = {};
  int krow_off = (lane & 7) + ((lane >> 4) << 3);   // ldsm4 x4 row pattern (2 n8-tiles)
  int khalf = (lane >> 3) & 1;
  int nkb = (r0 >> 6) + 1;                          // causal: blocks of 64 cols

  for (int kbk = 0; kbk < nkb; kbk++) {
    int cb = kbk * 64;
    unsigned kf[4][4];
#pragma unroll
    for (int i = 0; i < 4; i++)
      ldsm4(kf[i], s2u(&ks[(cb + i * 16 + krow_off) * 24 + khalf * 8]));
    unsigned pa[2][4][4];
#pragma unroll
    for (int mt = 0; mt < 2; mt++) {
      int ra = r0 + mt * 16 + gid, rb = ra + 8;
      float s[8][4];
#pragma unroll
      for (int nt = 0; nt < 8; nt++) {
        s[nt][0] = s[nt][1] = s[nt][2] = s[nt][3] = 0.0f;
        mma_bf16(s[nt], qa[mt], kf[nt >> 1][(nt & 1) * 2], kf[nt >> 1][(nt & 1) * 2 + 1]);
      }
#pragma unroll
      for (int nt = 0; nt < 8; nt++) {
        int c0 = cb + nt * 8 + 2 * tig;
        float p0 = (c0     <= ra) ? __expf(s[nt][0] * 0.25f) : 0.0f;
        float p1 = (c0 + 1 <= ra) ? __expf(s[nt][1] * 0.25f) : 0.0f;
        float p2 = (c0     <= rb) ? __expf(s[nt][2] * 0.25f) : 0.0f;
        float p3 = (c0 + 1 <= rb) ? __expf(s[nt][3] * 0.25f) : 0.0f;
        lsum[mt][0] += p0 + p1;
        lsum[mt][1] += p2 + p3;
        int kc = nt >> 1, hi = nt & 1;
        pa[mt][kc][hi * 2 + 0] = pack_bf2(p0, p1);
        pa[mt][kc][hi * 2 + 1] = pack_bf2(p2, p3);
      }
    }
#pragma unroll
    for (int kc = 0; kc < 4; kc++) {
      unsigned vt[4];
      ldsm4t(vt, s2u(&vs[(cb + kc * 16 + lrow) * 24 + lsel * 8]));
#pragma unroll
      for (int mt = 0; mt < 2; mt++) {
        mma_bf16(o[mt][0], pa[mt][kc], vt[0], vt[1]);
        mma_bf16(o[mt][1], pa[mt][kc], vt[2], vt[3]);
      }
    }
  }
#pragma unroll
  for (int mt = 0; mt < 2; mt++)
#pragma unroll
    for (int rr = 0; rr < 2; rr++) {
      float v = lsum[mt][rr];
      v += __shfl_xor_sync(0xffffffffu, v, 1);
      v += __shfl_xor_sync(0xffffffffu, v, 2);
      lsum[mt][rr] = 1.0f / v;
    }
  int b_ = bh / 6, h_ = bh % 6;
#pragma unroll
  for (int mt = 0; mt < 2; mt++) {
    int ra = r0 + mt * 16 + gid, rb = ra + 8;
#pragma unroll
    for (int nt = 0; nt < 2; nt++) {
      int c = nt * 8 + 2 * tig;
      *reinterpret_cast<__nv_bfloat162*>(&g_h[((size_t)(b_ * 256 + ra)) * 96 + h_ * 16 + c]) =
          __float22bfloat162_rn(make_float2(o[mt][nt][0] * lsum[mt][0], o[mt][nt][1] * lsum[mt][0]));
      *reinterpret_cast<__nv_bfloat162*>(&g_h[((size_t)(b_ * 256 + rb)) * 96 + h_ * 16 + c]) =
          __float22bfloat162_rn(make_float2(o[mt][nt][2] * lsum[mt][1], o[mt][nt][3] * lsum[mt][1]));
    }
  }
}

// ---- projection + residual + noise1 (A and B both cp.async) ----
__global__ void __launch_bounds__(384, 2) proj_kernel(const float* __restrict__ bp,
                                                      const float* __restrict__ x,
                                                      unsigned nk0, unsigned nk1v) {
  GEMM_PROLOG
  CPA_A(g_h, 96, 0)
  CPA_B(sm_b0, g_wp, 96, 0)
  CP_COMMIT;
  CP_WAIT(0);
  __syncthreads();
  float acc[2][4][4] = {};
  MMA_K96_BF16(sm_b0)
#pragma unroll
  for (int mt = 0; mt < 2; mt++)
#pragma unroll
    for (int nt = 0; nt < 4; nt++) {
      int r0 = row0 + wr * 32 + mt * 16 + gid;
      int c0 = wc * 32 + nt * 8 + 2 * tig;
      float bp0 = bp[c0], bp1 = bp[c0 + 1];
#pragma unroll
      for (int rr = 0; rr < 2; rr++) {
        int i0 = (r0 + rr * 8) * 96 + c0;
        float o0 = x[i0]     + acc[mt][nt][2 * rr]     + bp0 + jax_noise(nk0, nk1v, (unsigned)i0);
        float o1 = x[i0 + 1] + acc[mt][nt][2 * rr + 1] + bp1 + jax_noise(nk0, nk1v, (unsigned)(i0 + 1));
        *reinterpret_cast<float2*>(&g_x1[i0]) = make_float2(o0, o1);
      }
    }
}

// ---- fused LN2 + FF1 (4 col groups, B double-buffered) ----
__global__ void __launch_bounds__(384, 2) ff1_kernel(const float* __restrict__ b1,
                                                     const float* __restrict__ ln2g,
                                                     const float* __restrict__ ln2b) {
  GEMM_PROLOG
  CPA_B(sm_b0, g_w1c, 384, 0)
  CP_COMMIT;
  LN_TO_SMEM(g_x1, ln2g, ln2b)
  for (int grp = 0; grp < 4; grp++) {
    int co = grp * 96;
    CP_WAIT(0);
    __syncthreads();
    if (grp < 3) {
      if (grp & 1) { CPA_B(sm_b0, g_w1c, 384, co + 96) }
      else         { CPA_B(sm_b1, g_w1c, 384, co + 96) }
      CP_COMMIT;
    }
    float acc[2][4][4] = {};
    if (grp & 1) { MMA_K96_BF16(sm_b1) } else { MMA_K96_BF16(sm_b0) }
#pragma unroll
    for (int mt = 0; mt < 2; mt++)
#pragma unroll
      for (int nt = 0; nt < 4; nt++) {
        int r0 = row0 + wr * 32 + mt * 16 + gid;
        int c0 = wc * 32 + nt * 8 + 2 * tig;
        float bb0 = b1[co + c0], bb1 = b1[co + c0 + 1];
#pragma unroll
        for (int rr = 0; rr < 2; rr++) {
          int tok = r0 + rr * 8;
          *reinterpret_cast<__nv_bfloat162*>(&g_f[(size_t)tok * 384 + co + c0]) =
              __float22bfloat162_rn(make_float2(fmaxf(acc[mt][nt][2 * rr] + bb0, 0.0f),
                                                fmaxf(acc[mt][nt][2 * rr + 1] + bb1, 0.0f)));
        }
      }
  }
}

// ---- FF2 + residual + noise2 -> out (K=384 in 4 chunks; B pipelined) ----
__global__ void __launch_bounds__(384, 2) ff2_kernel(const float* __restrict__ b2,
                                                     float* __restrict__ out,
                                                     unsigned nk0, unsigned nk1v) {
  GEMM_PROLOG
  CPA_B(sm_b0, g_w2c, 96, 0)
  CP_COMMIT;
  float acc[2][4][4] = {};
#pragma unroll
  for (int g = 0; g < 4; g++) {
    __syncthreads();
    CPA_A(g_f, 384, g * 96)
    CP_COMMIT;
    if (g < 3) {
      const __nv_bfloat16* src = g_w2c + (g + 1) * 9216;
      if (g & 1) { CPA_B(sm_b0, src, 96, 0) }
      else       { CPA_B(sm_b1, src, 96, 0) }
      CP_COMMIT;
    }
    if (g < 3) { CP_WAIT(1); } else { CP_WAIT(0); }
    __syncthreads();
    if (g & 1) { MMA_K96_BF16(sm_b1) } else { MMA_K96_BF16(sm_b0) }
  }
#pragma unroll
  for (int mt = 0; mt < 2; mt++)
#pragma unroll
    for (int nt = 0; nt < 4; nt++) {
      int r0 = row0 + wr * 32 + mt * 16 + gid;
      int c0 = wc * 32 + nt * 8 + 2 * tig;
      float bb0 = b2[c0], bb1 = b2[c0 + 1];
#pragma unroll
      for (int rr = 0; rr < 2; rr++) {
        int i0 = (r0 + rr * 8) * 96 + c0;
        float o0 = g_x1[i0]     + acc[mt][nt][2 * rr]     + bb0 + jax_noise(nk0, nk1v, (unsigned)i0);
        float o1 = g_x1[i0 + 1] + acc[mt][nt][2 * rr + 1] + bb1 + jax_noise(nk0, nk1v, (unsigned)(i0 + 1));
        *reinterpret_cast<float2*>(&out[i0]) = make_float2(o0, o1);
      }
    }
}

extern "C" void kernel_launch(void* const* d_in, const int* in_sizes, int n_in,
                              void* d_out, int out_size) {
  (void)in_sizes; (void)n_in; (void)out_size;
  const float* x    = (const float*)d_in[0];
  const float* Wq   = (const float*)d_in[1];
  const float* Wk   = (const float*)d_in[2];
  const float* Wv   = (const float*)d_in[3];
  const float* Wp   = (const float*)d_in[4];
  const float* bp   = (const float*)d_in[5];
  const float* ln1g = (const float*)d_in[6];
  const float* ln1b = (const float*)d_in[7];
  const float* ln2g = (const float*)d_in[8];
  const float* ln2b = (const float*)d_in[9];
  const float* W1   = (const float*)d_in[10];
  const float* b1   = (const float*)d_in[11];
  const float* W2   = (const float*)d_in[12];
  const float* b2   = (const float*)d_in[13];
  float* out = (float*)d_out;

  unsigned nk1_0, nk1_1, nk2_0, nk2_1;
  tf2x32(0u, 42u, 0u, 0u, nk1_0, nk1_1);
  tf2x32(0u, 42u, 0u, 1u, nk2_0, nk2_1);

  cudaFuncSetAttribute(qkv_kernel,  cudaFuncAttributeMaxDynamicSharedMemorySize, SMEM_BYTES);
  cudaFuncSetAttribute(proj_kernel, cudaFuncAttributeMaxDynamicSharedMemorySize, SMEM_BYTES);
  cudaFuncSetAttribute(ff1_kernel,  cudaFuncAttributeMaxDynamicSharedMemorySize, SMEM_BYTES);
  cudaFuncSetAttribute(ff2_kernel,  cudaFuncAttributeMaxDynamicSharedMemorySize, SMEM_BYTES);

  prep_kernel<<<324, 256>>>(Wq, Wk, Wv, Wp, W1, W2);
  qkv_kernel <<<512, 384, SMEM_BYTES>>>(x, ln1g, ln1b);
  attn_kernel<<<1536, 256>>>();
  proj_kernel<<<512, 384, SMEM_BYTES>>>(bp, x, nk1_0, nk1_1);
  ff1_kernel <<<512, 384, SMEM_BYTES>>>(b1, ln2g, ln2b);
  ff2_kernel <<<512, 384, SMEM_BYTES>>>(b2, out, nk2_0, nk2_1);
}